// round 12
// baseline (speedup 1.0000x reference)
#include <cuda_runtime.h>
#include <cuda_fp16.h>
#include <math.h>

// ---------------------------------------------------------------------------
// MemTransformerLMEncoder - fp16 mma.sync; cp.async.cg (L1-bypass) fills,
// BK=64 2-stage GEMM, register-resident-P flash attention.
// Dead code: UpdateAttn branch + mem input unused. new_mem = hids[:,1008:1024].
// OutputAttn = 1024-key softmax with keys >=1008 double-weighted.
// tcgen05 unavailable (harness PTX targets sm_103) - mma.sync path.
// ---------------------------------------------------------------------------

#define D_MODEL 1024
#define SEQ     1024
#define BATCH   4
#define NHEAD   16
#define DHEAD   64
#define MROWS   (BATCH*SEQ)            // 4096
#define OUT_MAIN (BATCH*SEQ*D_MODEL)   // 4194304

// fp32 scratch
__device__ float g_hids0[MROWS*D_MODEL];
__device__ float g_proj[MROWS*D_MODEL];
__device__ float g_hids[MROWS*D_MODEL];
__device__ float g_outattn[MROWS*D_MODEL];
__device__ float g_pos[SEQ*D_MODEL];
// fp16 scratch
__device__ __half g_h0h[MROWS*D_MODEL];
__device__ __half g_qkvh[MROWS*3*D_MODEL];
__device__ __half g_attnh[MROWS*D_MODEL];
__device__ __half g_hidsh[MROWS*D_MODEL];
__device__ __half g_outh[MROWS*D_MODEL];
// fp16 transposed weights
__device__ __half g_wTa[3*D_MODEL*D_MODEL];
__device__ __half g_wTo[3*D_MODEL*D_MODEL];
__device__ __half g_wTaow[D_MODEL*D_MODEL];
__device__ __half g_wToow[D_MODEL*D_MODEL];
__device__ __half g_wTff2[D_MODEL*D_MODEL];

// ---------------------------------------------------------------------------
__device__ __forceinline__ void mma16(float* c, const unsigned* a, unsigned b0, unsigned b1) {
    asm volatile(
        "mma.sync.aligned.m16n8k16.row.col.f32.f16.f16.f32 "
        "{%0,%1,%2,%3}, {%4,%5,%6,%7}, {%8,%9}, {%0,%1,%2,%3};"
        : "+f"(c[0]), "+f"(c[1]), "+f"(c[2]), "+f"(c[3])
        : "r"(a[0]), "r"(a[1]), "r"(a[2]), "r"(a[3]), "r"(b0), "r"(b1));
}
__device__ __forceinline__ void ldsm4(unsigned* r, unsigned addr) {
    asm volatile("ldmatrix.sync.aligned.m8n8.x4.shared.b16 {%0,%1,%2,%3}, [%4];"
        : "=r"(r[0]), "=r"(r[1]), "=r"(r[2]), "=r"(r[3]) : "r"(addr));
}
__device__ __forceinline__ void ldsm4t(unsigned* r, unsigned addr) {
    asm volatile("ldmatrix.sync.aligned.m8n8.x4.trans.shared.b16 {%0,%1,%2,%3}, [%4];"
        : "=r"(r[0]), "=r"(r[1]), "=r"(r[2]), "=r"(r[3]) : "r"(addr));
}
// L1-bypass async copy: fills smem from L2 directly (keeps L1TEX free for ldmatrix)
__device__ __forceinline__ void cp16(unsigned dst, const void* src) {
    asm volatile("cp.async.cg.shared.global [%0], [%1], 16;" :: "r"(dst), "l"(src));
}
__device__ __forceinline__ int off16(int lane, int STR) {
    return ((lane & 7) + ((lane >> 3) & 1) * 8) * STR + ((lane >> 4) & 1) * 8;
}
__device__ __forceinline__ int off16v(int lane, int STR) {
    return ((lane & 7) + ((lane >> 4) & 1) * 8) * STR + ((lane >> 3) & 1) * 8;
}
__device__ __forceinline__ unsigned packh2(float a, float b) {
    __half2 h = __floats2half2_rn(a, b);
    return *(unsigned*)&h;
}

// ---------------------------------------------------------------------------
// Positional table (depends only on s,d).
// ---------------------------------------------------------------------------
__global__ void pos_kernel(float* __restrict__ pos) {
    int idx = blockIdx.x * 256 + threadIdx.x;
    int d = idx & (D_MODEL - 1);
    int s = idx >> 10;
    float freq  = powf(10000.0f, -(float)(d & ~1) * (1.0f / 1024.0f));
    float angle = (float)s * freq;
    pos[idx] = (d & 1) ? cosf(angle) : sinf(angle);
}

__global__ void embed_kernel(const int* __restrict__ data,
                             const float* __restrict__ emb,
                             const float* __restrict__ pos,
                             float* __restrict__ outf, __half* __restrict__ outh) {
    int idx = blockIdx.x * 256 + threadIdx.x;
    int d  = idx & (D_MODEL - 1);
    int bs = idx >> 10;
    int s  = bs & (SEQ - 1);
    int tok = data[bs];
    float v = emb[(size_t)tok * D_MODEL + d] * 32.0f + pos[(s << 10) + d];
    outf[idx] = v;
    outh[idx] = __float2half(v);
}

// ---------------------------------------------------------------------------
// Fused transpose+fp16 convert: 9 units of 1024x1024
// ---------------------------------------------------------------------------
struct TpArgs {
    const float* src[9];
    __half* dst[9];
    int ld[9];
};
__global__ void transpose_h_kernel(TpArgs a) {
    __shared__ float tile[32][33];
    int u = blockIdx.z;
    const float* src = a.src[u];
    __half* dst = a.dst[u];
    int ld = a.ld[u];
    int kb = blockIdx.y * 32, nb = blockIdx.x * 32;
    int tx = threadIdx.x, ty = threadIdx.y;
    #pragma unroll
    for (int i = 0; i < 32; i += 8)
        tile[ty + i][tx] = src[(size_t)(kb + ty + i) * ld + nb + tx];
    __syncthreads();
    #pragma unroll
    for (int i = 0; i < 32; i += 8)
        dst[(size_t)(nb + ty + i) * 1024 + kb + tx] = __float2half(tile[tx][ty + i]);
}

// ---------------------------------------------------------------------------
// fp16 GEMM, 4 warps (128 thr), 64x64 warp tiles, CTA tile 128x128, BK=64,
// 2-stage cp.async.cg, ldmatrix. C = A[M,K] @ B[N,K]^T (+fp32 resid).
// Row stride 72 halves (144B = 9x16B, odd) -> conflict-free ldsm + cp.async.
// ---------------------------------------------------------------------------
#define GSTR 72
#define GAB  (128*GSTR*2)               // bytes per A (or B) buffer = 18432
#define GSMEM (2*2*GAB)                 // 73728

template<bool OUTH>
__global__ __launch_bounds__(128, 2)
void gemm_h(const __half* __restrict__ A, const __half* __restrict__ B,
            const float* __restrict__ resid, void* __restrict__ Cg,
            int K, int lda, int ldb, int ldc) {
    extern __shared__ __align__(16) char smraw[];
    const int tid = threadIdx.x, lane = tid & 31, warp = tid >> 5;
    const int row0 = blockIdx.y * 128, col0 = blockIdx.x * 128;
    const int wm = (warp & 1) * 64, wn = (warp >> 1) * 64;
    const unsigned smBase = (unsigned)__cvta_generic_to_shared(smraw);
    const int offL = off16(lane, GSTR);

    float acc[4][8][4];
    #pragma unroll
    for (int mi = 0; mi < 4; mi++)
        #pragma unroll
        for (int ni = 0; ni < 8; ni++)
            #pragma unroll
            for (int c = 0; c < 4; c++) acc[mi][ni][c] = 0.0f;

    const int T = K / 64;

    auto loadTile = [&](int t) {
        int buf = t & 1;
        unsigned aB = smBase + (unsigned)(buf * 2 * GAB);
        unsigned bB = aB + GAB;
        const __half* Asrc = A + (size_t)row0 * lda + t * 64;
        const __half* Bsrc = B + (size_t)col0 * ldb + t * 64;
        #pragma unroll
        for (int s = 0; s < 8; s++) {
            int c = tid + 128 * s;              // 0..1023
            int m = c >> 3, kc = (c & 7) * 8;
            cp16(aB + (unsigned)(m * GSTR + kc) * 2u, Asrc + (size_t)m * lda + kc);
        }
        #pragma unroll
        for (int s = 0; s < 8; s++) {
            int c = tid + 128 * s;
            int n = c >> 3, kc = (c & 7) * 8;
            cp16(bB + (unsigned)(n * GSTR + kc) * 2u, Bsrc + (size_t)n * ldb + kc);
        }
    };

    loadTile(0);
    asm volatile("cp.async.commit_group;" ::: "memory");

    for (int t = 0; t < T; t++) {
        if (t + 1 < T) {
            loadTile(t + 1);
            asm volatile("cp.async.commit_group;" ::: "memory");
            asm volatile("cp.async.wait_group 1;" ::: "memory");
        } else {
            asm volatile("cp.async.wait_group 0;" ::: "memory");
        }
        __syncthreads();

        int buf = t & 1;
        unsigned aB = smBase + (unsigned)(buf * 2 * GAB);
        unsigned bB = aB + GAB;
        #pragma unroll
        for (int kk = 0; kk < 64; kk += 16) {
            unsigned af[4][4];
            #pragma unroll
            for (int mi = 0; mi < 4; mi++)
                ldsm4(af[mi], aB + (unsigned)((wm + mi * 16) * GSTR + kk + offL) * 2u);
            #pragma unroll
            for (int g = 0; g < 4; g++) {
                unsigned bf[4];
                ldsm4(bf, bB + (unsigned)((wn + g * 16) * GSTR + kk + offL) * 2u);
                #pragma unroll
                for (int mi = 0; mi < 4; mi++) {
                    mma16(acc[mi][2 * g],     af[mi], bf[0], bf[2]);
                    mma16(acc[mi][2 * g + 1], af[mi], bf[1], bf[3]);
                }
            }
        }
        __syncthreads();
    }

    {
        int q = lane >> 2, r2 = (lane & 3) * 2;
        #pragma unroll
        for (int mi = 0; mi < 4; mi++) {
            int row = row0 + wm + mi * 16 + q;
            #pragma unroll
            for (int ni = 0; ni < 8; ni++) {
                int col = col0 + wn + ni * 8 + r2;
                float v0 = acc[mi][ni][0], v1 = acc[mi][ni][1];
                float v2 = acc[mi][ni][2], v3 = acc[mi][ni][3];
                if (resid) {
                    float2 r0 = *(const float2*)&resid[(size_t)row * ldc + col];
                    float2 r1 = *(const float2*)&resid[(size_t)(row + 8) * ldc + col];
                    v0 += r0.x; v1 += r0.y; v2 += r1.x; v3 += r1.y;
                }
                if (OUTH) {
                    __half2* C = (__half2*)Cg;
                    C[((size_t)row * ldc + col) >> 1]       = __floats2half2_rn(v0, v1);
                    C[((size_t)(row + 8) * ldc + col) >> 1] = __floats2half2_rn(v2, v3);
                } else {
                    float* C = (float*)Cg;
                    *(float2*)&C[(size_t)row * ldc + col]       = make_float2(v0, v1);
                    *(float2*)&C[(size_t)(row + 8) * ldc + col] = make_float2(v2, v3);
                }
            }
        }
    }
}

// ---------------------------------------------------------------------------
// Flash attention, register-resident P (round-10 proven, now with .cg fills).
// ---------------------------------------------------------------------------
#define FSTR 72
#define FKH  9216
#define FVH  18432
#define FKVB 4608
#define FA_SMEM 55296

__global__ __launch_bounds__(256, 2)
void flash_h(const __half* __restrict__ qkv, __half* __restrict__ O, int extraFlag) {
    extern __shared__ __align__(16) char smraw[];
    const int tid = threadIdx.x, lane = tid & 31, warp = tid >> 5;
    const int wm = warp * 16;
    const int qb = blockIdx.x, bh = blockIdx.y;
    const int b = bh >> 4, h = bh & 15;
    const int qrow0 = qb * 128;

    const unsigned smBase = (unsigned)__cvta_generic_to_shared(smraw);
    const int offL = off16(lane, FSTR);
    const int offV = off16v(lane, FSTR);

    const __half* base = qkv + (size_t)(b * SEQ) * 3072 + h * 64;

    {
        const __half* Qsrc = base + (size_t)qrow0 * 3072;
        #pragma unroll
        for (int s = 0; s < 4; s++) {
            int c = tid + 256 * s;
            int m = c >> 3, kc = (c & 7) * 8;
            cp16(smBase + (unsigned)(m * FSTR + kc) * 2u, Qsrc + (size_t)m * 3072 + kc);
        }
    }
    auto loadKV = [&](int t) {
        int buf = t & 1;
        unsigned kB = smBase + (unsigned)(FKH + buf * FKVB) * 2u;
        unsigned vB = smBase + (unsigned)(FVH + buf * FKVB) * 2u;
        const __half* Ksrc = base + (size_t)(t * 64) * 3072 + 1024;
        const __half* Vsrc = base + (size_t)(t * 64) * 3072 + 2048;
        #pragma unroll
        for (int s = 0; s < 2; s++) {
            int c = tid + 256 * s;
            int n = c >> 3, kc = (c & 7) * 8;
            cp16(kB + (unsigned)(n * FSTR + kc) * 2u, Ksrc + (size_t)n * 3072 + kc);
            cp16(vB + (unsigned)(n * FSTR + kc) * 2u, Vsrc + (size_t)n * 3072 + kc);
        }
    };
    loadKV(0);
    asm volatile("cp.async.commit_group;" ::: "memory");

    float m0 = -INFINITY, m1 = -INFINITY, l0 = 0.0f, l1 = 0.0f;
    float oacc[8][4];
    #pragma unroll
    for (int ni = 0; ni < 8; ni++)
        #pragma unroll
        for (int c = 0; c < 4; c++) oacc[ni][c] = 0.0f;

    for (int t = 0; t < 16; t++) {
        if (t + 1 < 16) {
            loadKV(t + 1);
            asm volatile("cp.async.commit_group;" ::: "memory");
            asm volatile("cp.async.wait_group 1;" ::: "memory");
        } else {
            asm volatile("cp.async.wait_group 0;" ::: "memory");
        }
        __syncthreads();

        int buf = t & 1;
        unsigned kB = smBase + (unsigned)(FKH + buf * FKVB) * 2u;
        unsigned vB = smBase + (unsigned)(FVH + buf * FKVB) * 2u;

        float sc[8][4];
        #pragma unroll
        for (int ni = 0; ni < 8; ni++)
            #pragma unroll
            for (int c = 0; c < 4; c++) sc[ni][c] = 0.0f;
        #pragma unroll
        for (int kki = 0; kki < 4; kki++) {
            int kk = kki * 16;
            unsigned af[4];
            ldsm4(af, smBase + (unsigned)(wm * FSTR + kk + offL) * 2u);
            #pragma unroll
            for (int g = 0; g < 4; g++) {
                unsigned bf[4];
                ldsm4(bf, kB + (unsigned)((g * 16) * FSTR + kk + offL) * 2u);
                mma16(sc[2 * g],     af, bf[0], bf[2]);
                mma16(sc[2 * g + 1], af, bf[1], bf[3]);
            }
        }

        float rm0 = -INFINITY, rm1 = -INFINITY;
        #pragma unroll
        for (int ni = 0; ni < 8; ni++) {
            sc[ni][0] *= 0.125f; sc[ni][1] *= 0.125f;
            sc[ni][2] *= 0.125f; sc[ni][3] *= 0.125f;
            rm0 = fmaxf(rm0, fmaxf(sc[ni][0], sc[ni][1]));
            rm1 = fmaxf(rm1, fmaxf(sc[ni][2], sc[ni][3]));
        }
        rm0 = fmaxf(rm0, __shfl_xor_sync(0xffffffff, rm0, 1));
        rm0 = fmaxf(rm0, __shfl_xor_sync(0xffffffff, rm0, 2));
        rm1 = fmaxf(rm1, __shfl_xor_sync(0xffffffff, rm1, 1));
        rm1 = fmaxf(rm1, __shfl_xor_sync(0xffffffff, rm1, 2));
        float nm0 = fmaxf(m0, rm0), nm1 = fmaxf(m1, rm1);
        float c0 = __expf(m0 - nm0), c1 = __expf(m1 - nm1);
        m0 = nm0; m1 = nm1;
        float s0 = 0.0f, s1 = 0.0f;
        bool dbl = extraFlag && (t == 15);
        #pragma unroll
        for (int ni = 0; ni < 8; ni++) {
            float p00 = __expf(sc[ni][0] - nm0);
            float p01 = __expf(sc[ni][1] - nm0);
            float p10 = __expf(sc[ni][2] - nm1);
            float p11 = __expf(sc[ni][3] - nm1);
            if (dbl && ni >= 6) { p00 *= 2.f; p01 *= 2.f; p10 *= 2.f; p11 *= 2.f; }
            s0 += p00 + p01; s1 += p10 + p11;
            sc[ni][0] = p00; sc[ni][1] = p01; sc[ni][2] = p10; sc[ni][3] = p11;
        }
        s0 += __shfl_xor_sync(0xffffffff, s0, 1);
        s0 += __shfl_xor_sync(0xffffffff, s0, 2);
        s1 += __shfl_xor_sync(0xffffffff, s1, 1);
        s1 += __shfl_xor_sync(0xffffffff, s1, 2);
        l0 = l0 * c0 + s0;
        l1 = l1 * c1 + s1;

        #pragma unroll
        for (int ni = 0; ni < 8; ni++) {
            oacc[ni][0] *= c0; oacc[ni][1] *= c0;
            oacc[ni][2] *= c1; oacc[ni][3] *= c1;
        }
        #pragma unroll
        for (int kki = 0; kki < 4; kki++) {
            int ni0 = 2 * kki;
            unsigned af2[4];
            af2[0] = packh2(sc[ni0][0],     sc[ni0][1]);
            af2[1] = packh2(sc[ni0][2],     sc[ni0][3]);
            af2[2] = packh2(sc[ni0 + 1][0], sc[ni0 + 1][1]);
            af2[3] = packh2(sc[ni0 + 1][2], sc[ni0 + 1][3]);
            #pragma unroll
            for (int g = 0; g < 4; g++) {
                unsigned bf[4];
                ldsm4t(bf, vB + (unsigned)((kki * 16) * FSTR + g * 16 + offV) * 2u);
                mma16(oacc[2 * g],     af2, bf[0], bf[2]);
                mma16(oacc[2 * g + 1], af2, bf[1], bf[3]);
            }
        }
        __syncthreads();
    }

    {
        int q = lane >> 2, r2c = (lane & 3) * 2;
        float i0 = 1.0f / l0, i1 = 1.0f / l1;
        int row0 = qrow0 + wm + q;
        #pragma unroll
        for (int ni = 0; ni < 8; ni++) {
            int col = h * 64 + ni * 8 + r2c;
            size_t g0 = (size_t)(b * SEQ + row0) * D_MODEL + col;
            size_t g1 = (size_t)(b * SEQ + row0 + 8) * D_MODEL + col;
            ((__half2*)O)[g0 >> 1] = __floats2half2_rn(oacc[ni][0] * i0, oacc[ni][1] * i0);
            ((__half2*)O)[g1 >> 1] = __floats2half2_rn(oacc[ni][2] * i1, oacc[ni][3] * i1);
        }
    }
}

// ---------------------------------------------------------------------------
// Reductions / LN
// ---------------------------------------------------------------------------
__device__ __forceinline__ float block_reduce_sum(float val, float* sdata) {
    int t = threadIdx.x;
    #pragma unroll
    for (int off = 16; off > 0; off >>= 1)
        val += __shfl_down_sync(0xffffffff, val, off);
    if ((t & 31) == 0) sdata[t >> 5] = val;
    __syncthreads();
    if (t < 32) {
        float v = (t < 8) ? sdata[t] : 0.0f;
        #pragma unroll
        for (int off = 4; off > 0; off >>= 1)
            v += __shfl_down_sync(0xffffffff, v, off);
        if (t == 0) sdata[0] = v;
    }
    __syncthreads();
    float r = sdata[0];
    __syncthreads();
    return r;
}

// LN; optionally also writes rows [1008,1024) of each batch to memout (new_mem)
__global__ __launch_bounds__(256)
void ln_kernel(const float* __restrict__ x, const float* __restrict__ g,
               const float* __restrict__ bb, float* __restrict__ outf,
               __half* __restrict__ outh, float* __restrict__ memout) {
    __shared__ float sdata[32];
    int row = blockIdx.x;
    int t = threadIdx.x;
    const float* xr = x + (size_t)row * D_MODEL;
    float v[4];
    #pragma unroll
    for (int i = 0; i < 4; i++) v[i] = xr[t + 256 * i];
    float s = v[0] + v[1] + v[2] + v[3];
    float mu = block_reduce_sum(s, sdata) * (1.0f / 1024.0f);
    float sq = 0.f;
    #pragma unroll
    for (int i = 0; i < 4; i++) { float d0 = v[i] - mu; sq += d0 * d0; }
    float var = block_reduce_sum(sq, sdata) * (1.0f / 1024.0f);
    float inv = 1.0f / sqrtf(var + 1e-5f);
    int srow = row & (SEQ - 1), bidx = row >> 10;
    bool isMem = memout && (srow >= 1008);
    float* mrow = isMem ? memout + ((size_t)(bidx * 16 + srow - 1008)) * D_MODEL : nullptr;
    #pragma unroll
    for (int i = 0; i < 4; i++) {
        int c = t + 256 * i;
        float o = (v[i] - mu) * inv * g[c] + bb[c];
        outf[(size_t)row * D_MODEL + c] = o;
        if (outh) outh[(size_t)row * D_MODEL + c] = __float2half(o);
        if (isMem) mrow[c] = o;
    }
}

__global__ __launch_bounds__(256)
void ln_ln_kernel(const float* __restrict__ proj,
                  const float* __restrict__ g1, const float* __restrict__ b1,
                  const float* __restrict__ hids,
                  const float* __restrict__ g2, const float* __restrict__ b2,
                  float* __restrict__ outf, __half* __restrict__ outh) {
    __shared__ float sdata[32];
    int row = blockIdx.x;
    int t = threadIdx.x;
    const float* xr = proj + (size_t)row * D_MODEL;
    const float* hr = hids + (size_t)row * D_MODEL;
    float v[4], hv[4];
    #pragma unroll
    for (int i = 0; i < 4; i++) { v[i] = xr[t + 256 * i]; hv[i] = hr[t + 256 * i]; }
    float s = v[0] + v[1] + v[2] + v[3];
    float mu = block_reduce_sum(s, sdata) * (1.0f / 1024.0f);
    float sq = 0.f;
    #pragma unroll
    for (int i = 0; i < 4; i++) { float d0 = v[i] - mu; sq += d0 * d0; }
    float var = block_reduce_sum(sq, sdata) * (1.0f / 1024.0f);
    float inv = 1.0f / sqrtf(var + 1e-5f);
    float y[4];
    #pragma unroll
    for (int i = 0; i < 4; i++) {
        int c = t + 256 * i;
        y[i] = hv[i] + (v[i] - mu) * inv * g1[c] + b1[c];
    }
    float s2 = y[0] + y[1] + y[2] + y[3];
    float mu2 = block_reduce_sum(s2, sdata) * (1.0f / 1024.0f);
    float sq2 = 0.f;
    #pragma unroll
    for (int i = 0; i < 4; i++) { float d0 = y[i] - mu2; sq2 += d0 * d0; }
    float var2 = block_reduce_sum(sq2, sdata) * (1.0f / 1024.0f);
    float inv2 = 1.0f / sqrtf(var2 + 1e-5f);
    #pragma unroll
    for (int i = 0; i < 4; i++) {
        int c = t + 256 * i;
        float o = (y[i] - mu2) * inv2 * g2[c] + b2[c];
        outf[(size_t)row * D_MODEL + c] = o;
        outh[(size_t)row * D_MODEL + c] = __float2half(o);
    }
}

// ---------------------------------------------------------------------------
static float *s_hids0 = 0, *s_proj = 0, *s_hids = 0, *s_outattn = 0, *s_pos = 0;
static __half *s_h0h = 0, *s_qkvh = 0, *s_attnh = 0, *s_hidsh = 0, *s_outh = 0;
static __half *s_wTa = 0, *s_wTo = 0, *s_wTaow = 0, *s_wToow = 0, *s_wTff2 = 0;

static void resolve_scratch() {
    if (s_hids0) return;
    cudaGetSymbolAddress((void**)&s_hids0,   g_hids0);
    cudaGetSymbolAddress((void**)&s_proj,    g_proj);
    cudaGetSymbolAddress((void**)&s_hids,    g_hids);
    cudaGetSymbolAddress((void**)&s_outattn, g_outattn);
    cudaGetSymbolAddress((void**)&s_pos,     g_pos);
    cudaGetSymbolAddress((void**)&s_h0h,     g_h0h);
    cudaGetSymbolAddress((void**)&s_qkvh,    g_qkvh);
    cudaGetSymbolAddress((void**)&s_attnh,   g_attnh);
    cudaGetSymbolAddress((void**)&s_hidsh,   g_hidsh);
    cudaGetSymbolAddress((void**)&s_outh,    g_outh);
    cudaGetSymbolAddress((void**)&s_wTa,     g_wTa);
    cudaGetSymbolAddress((void**)&s_wTo,     g_wTo);
    cudaGetSymbolAddress((void**)&s_wTaow,   g_wTaow);
    cudaGetSymbolAddress((void**)&s_wToow,   g_wToow);
    cudaGetSymbolAddress((void**)&s_wTff2,   g_wTff2);
    cudaFuncSetAttribute(gemm_h<false>, cudaFuncAttributeMaxDynamicSharedMemorySize, GSMEM);
    cudaFuncSetAttribute(gemm_h<true>,  cudaFuncAttributeMaxDynamicSharedMemorySize, GSMEM);
    cudaFuncSetAttribute(flash_h, cudaFuncAttributeMaxDynamicSharedMemorySize, FA_SMEM);
}

static void run_attention(const __half* xh, const __half* wT, int extraFlag) {
    gemm_h<true><<<dim3(24, 32), 128, GSMEM>>>(
        xh, wT, nullptr, s_qkvh, 1024, 1024, 1024, 3072);
    flash_h<<<dim3(8, BATCH * NHEAD), 256, FA_SMEM>>>(s_qkvh, s_attnh, extraFlag);
}

extern "C" void kernel_launch(void* const* d_in, const int* in_sizes, int n_in,
                              void* d_out, int out_size) {
    const int*   data  = (const int*)d_in[0];
    const float* emb   = (const float*)d_in[2];
    const float* a_qw  = (const float*)d_in[3];
    const float* a_kvw = (const float*)d_in[4];
    const float* a_ow  = (const float*)d_in[5];
    const float* a_g   = (const float*)d_in[6];
    const float* a_b   = (const float*)d_in[7];
    const float* o_qw  = (const float*)d_in[16];
    const float* o_kvw = (const float*)d_in[17];
    const float* o_ow  = (const float*)d_in[18];
    const float* o_g   = (const float*)d_in[19];
    const float* o_b   = (const float*)d_in[20];
    const float* ff2_w = (const float*)d_in[21];
    const float* ln1_g = (const float*)d_in[22];
    const float* ln1_b = (const float*)d_in[23];
    const float* ln2_g = (const float*)d_in[24];
    const float* ln2_b = (const float*)d_in[25];
    float* out = (float*)d_out;

    resolve_scratch();

    TpArgs tp;
    tp.src[0] = a_qw;          tp.dst[0] = s_wTa;               tp.ld[0] = 1024;
    tp.src[1] = a_kvw;         tp.dst[1] = s_wTa + 1024*1024;   tp.ld[1] = 2048;
    tp.src[2] = a_kvw + 1024;  tp.dst[2] = s_wTa + 2*1024*1024; tp.ld[2] = 2048;
    tp.src[3] = o_qw;          tp.dst[3] = s_wTo;               tp.ld[3] = 1024;
    tp.src[4] = o_kvw;         tp.dst[4] = s_wTo + 1024*1024;   tp.ld[4] = 2048;
    tp.src[5] = o_kvw + 1024;  tp.dst[5] = s_wTo + 2*1024*1024; tp.ld[5] = 2048;
    tp.src[6] = a_ow;          tp.dst[6] = s_wTaow;             tp.ld[6] = 1024;
    tp.src[7] = o_ow;          tp.dst[7] = s_wToow;             tp.ld[7] = 1024;
    tp.src[8] = ff2_w;         tp.dst[8] = s_wTff2;             tp.ld[8] = 1024;
    transpose_h_kernel<<<dim3(32, 32, 9), dim3(32, 8)>>>(tp);

    pos_kernel<<<(SEQ * D_MODEL) / 256, 256>>>(s_pos);
    embed_kernel<<<OUT_MAIN / 256, 256>>>(data, emb, s_pos, s_hids0, s_h0h);

    // self attention (layer)
    run_attention(s_h0h, s_wTa, 0);
    gemm_h<false><<<dim3(8, 32), 128, GSMEM>>>(
        s_attnh, s_wTaow, s_hids0, s_proj, 1024, 1024, 1024, 1024);
    // LN + fused new_mem extraction (rows 1008..1023 per batch)
    ln_kernel<<<MROWS, 256>>>(s_proj, a_g, a_b, s_hids, s_hidsh, out + OUT_MAIN);

    // OutputAttn (keys >= 1008 double-weighted)
    run_attention(s_hidsh, s_wTo, 1);
    gemm_h<false><<<dim3(8, 32), 128, GSMEM>>>(
        s_attnh, s_wToow, s_hids, s_proj, 1024, 1024, 1024, 1024);
    ln_ln_kernel<<<MROWS, 256>>>(s_proj, o_g, o_b, s_hids, ln1_g, ln1_b, s_outattn, s_outh);

    gemm_h<false><<<dim3(8, 32), 128, GSMEM>>>(
        s_outh, s_wTff2, s_outattn, s_proj, 1024, 1024, 1024, 1024);
    ln_kernel<<<MROWS, 256>>>(s_proj, ln2_g, ln2_b, out, nullptr, nullptr);
}

// round 13
// speedup vs baseline: 1.0083x; 1.0083x over previous
#include <cuda_runtime.h>
#include <cuda_fp16.h>
#include <math.h>

// ---------------------------------------------------------------------------
// MemTransformerLMEncoder - fp16 mma.sync everywhere; fp16 residual stream
// (fp32 only inside LN math and for proj/out buffers).
// Dead code: UpdateAttn branch + mem input unused. new_mem = hids[:,1008:1024].
// OutputAttn = 1024-key softmax with keys >=1008 double-weighted.
// HMMA (mma.sync) structural ceiling ~250 TF/s on this path; tcgen05 blocked
// by harness compute_103 virtual arch. This round trims elementwise traffic.
// ---------------------------------------------------------------------------

#define D_MODEL 1024
#define SEQ     1024
#define BATCH   4
#define NHEAD   16
#define DHEAD   64
#define MROWS   (BATCH*SEQ)            // 4096
#define OUT_MAIN (BATCH*SEQ*D_MODEL)   // 4194304

// fp32 scratch
__device__ float g_proj[MROWS*D_MODEL];
__device__ float g_pos[SEQ*D_MODEL];
// fp16 scratch
__device__ __half g_h0h[MROWS*D_MODEL];
__device__ __half g_qkvh[MROWS*3*D_MODEL];
__device__ __half g_attnh[MROWS*D_MODEL];
__device__ __half g_hidsh[MROWS*D_MODEL];
__device__ __half g_outh[MROWS*D_MODEL];
// fp16 transposed weights
__device__ __half g_wTa[3*D_MODEL*D_MODEL];
__device__ __half g_wTo[3*D_MODEL*D_MODEL];
__device__ __half g_wTaow[D_MODEL*D_MODEL];
__device__ __half g_wToow[D_MODEL*D_MODEL];
__device__ __half g_wTff2[D_MODEL*D_MODEL];

// ---------------------------------------------------------------------------
__device__ __forceinline__ void mma16(float* c, const unsigned* a, unsigned b0, unsigned b1) {
    asm volatile(
        "mma.sync.aligned.m16n8k16.row.col.f32.f16.f16.f32 "
        "{%0,%1,%2,%3}, {%4,%5,%6,%7}, {%8,%9}, {%0,%1,%2,%3};"
        : "+f"(c[0]), "+f"(c[1]), "+f"(c[2]), "+f"(c[3])
        : "r"(a[0]), "r"(a[1]), "r"(a[2]), "r"(a[3]), "r"(b0), "r"(b1));
}
__device__ __forceinline__ void ldsm4(unsigned* r, unsigned addr) {
    asm volatile("ldmatrix.sync.aligned.m8n8.x4.shared.b16 {%0,%1,%2,%3}, [%4];"
        : "=r"(r[0]), "=r"(r[1]), "=r"(r[2]), "=r"(r[3]) : "r"(addr));
}
__device__ __forceinline__ void ldsm4t(unsigned* r, unsigned addr) {
    asm volatile("ldmatrix.sync.aligned.m8n8.x4.trans.shared.b16 {%0,%1,%2,%3}, [%4];"
        : "=r"(r[0]), "=r"(r[1]), "=r"(r[2]), "=r"(r[3]) : "r"(addr));
}
__device__ __forceinline__ void cp16(unsigned dst, const void* src) {
    asm volatile("cp.async.cg.shared.global [%0], [%1], 16;" :: "r"(dst), "l"(src));
}
__device__ __forceinline__ int off16(int lane, int STR) {
    return ((lane & 7) + ((lane >> 3) & 1) * 8) * STR + ((lane >> 4) & 1) * 8;
}
__device__ __forceinline__ int off16v(int lane, int STR) {
    return ((lane & 7) + ((lane >> 4) & 1) * 8) * STR + ((lane >> 3) & 1) * 8;
}
__device__ __forceinline__ unsigned packh2(float a, float b) {
    __half2 h = __floats2half2_rn(a, b);
    return *(unsigned*)&h;
}

// ---------------------------------------------------------------------------
// Positional table (depends only on s,d).
// ---------------------------------------------------------------------------
__global__ void pos_kernel(float* __restrict__ pos) {
    int idx = blockIdx.x * 256 + threadIdx.x;
    int d = idx & (D_MODEL - 1);
    int s = idx >> 10;
    float freq  = powf(10000.0f, -(float)(d & ~1) * (1.0f / 1024.0f));
    float angle = (float)s * freq;
    pos[idx] = (d & 1) ? cosf(angle) : sinf(angle);
}

// Embedding * sqrt(D) + pos gather -> fp16 only (residual stream is fp16)
__global__ void embed_kernel(const int* __restrict__ data,
                             const float* __restrict__ emb,
                             const float* __restrict__ pos,
                             __half* __restrict__ outh) {
    int idx = blockIdx.x * 256 + threadIdx.x;
    int d  = idx & (D_MODEL - 1);
    int bs = idx >> 10;
    int s  = bs & (SEQ - 1);
    int tok = data[bs];
    float v = emb[(size_t)tok * D_MODEL + d] * 32.0f + pos[(s << 10) + d];
    outh[idx] = __float2half(v);
}

// ---------------------------------------------------------------------------
// Fused transpose+fp16 convert: 9 units of 1024x1024
// ---------------------------------------------------------------------------
struct TpArgs {
    const float* src[9];
    __half* dst[9];
    int ld[9];
};
__global__ void transpose_h_kernel(TpArgs a) {
    __shared__ float tile[32][33];
    int u = blockIdx.z;
    const float* src = a.src[u];
    __half* dst = a.dst[u];
    int ld = a.ld[u];
    int kb = blockIdx.y * 32, nb = blockIdx.x * 32;
    int tx = threadIdx.x, ty = threadIdx.y;
    #pragma unroll
    for (int i = 0; i < 32; i += 8)
        tile[ty + i][tx] = src[(size_t)(kb + ty + i) * ld + nb + tx];
    __syncthreads();
    #pragma unroll
    for (int i = 0; i < 32; i += 8)
        dst[(size_t)(nb + ty + i) * 1024 + kb + tx] = __float2half(tile[tx][ty + i]);
}

// ---------------------------------------------------------------------------
// fp16 GEMM, 4 warps, 64x64 warp tiles, CTA 128x128, BK=64, 2-stage cp.async.
// C = A[M,K] @ B[N,K]^T (+fp16 resid). OUTH: fp16 C, else fp32 C.
// ---------------------------------------------------------------------------
#define GSTR 72
#define GAB  (128*GSTR*2)               // 18432 bytes per buffer
#define GSMEM (2*2*GAB)                 // 73728

template<bool OUTH>
__global__ __launch_bounds__(128, 2)
void gemm_h(const __half* __restrict__ A, const __half* __restrict__ B,
            const __half* __restrict__ resid, void* __restrict__ Cg,
            int K, int lda, int ldb, int ldc) {
    extern __shared__ __align__(16) char smraw[];
    const int tid = threadIdx.x, lane = tid & 31, warp = tid >> 5;
    const int row0 = blockIdx.y * 128, col0 = blockIdx.x * 128;
    const int wm = (warp & 1) * 64, wn = (warp >> 1) * 64;
    const unsigned smBase = (unsigned)__cvta_generic_to_shared(smraw);
    const int offL = off16(lane, GSTR);

    float acc[4][8][4];
    #pragma unroll
    for (int mi = 0; mi < 4; mi++)
        #pragma unroll
        for (int ni = 0; ni < 8; ni++)
            #pragma unroll
            for (int c = 0; c < 4; c++) acc[mi][ni][c] = 0.0f;

    const int T = K / 64;

    auto loadTile = [&](int t) {
        int buf = t & 1;
        unsigned aB = smBase + (unsigned)(buf * 2 * GAB);
        unsigned bB = aB + GAB;
        const __half* Asrc = A + (size_t)row0 * lda + t * 64;
        const __half* Bsrc = B + (size_t)col0 * ldb + t * 64;
        #pragma unroll
        for (int s = 0; s < 8; s++) {
            int c = tid + 128 * s;
            int m = c >> 3, kc = (c & 7) * 8;
            cp16(aB + (unsigned)(m * GSTR + kc) * 2u, Asrc + (size_t)m * lda + kc);
        }
        #pragma unroll
        for (int s = 0; s < 8; s++) {
            int c = tid + 128 * s;
            int n = c >> 3, kc = (c & 7) * 8;
            cp16(bB + (unsigned)(n * GSTR + kc) * 2u, Bsrc + (size_t)n * ldb + kc);
        }
    };

    loadTile(0);
    asm volatile("cp.async.commit_group;" ::: "memory");

    for (int t = 0; t < T; t++) {
        if (t + 1 < T) {
            loadTile(t + 1);
            asm volatile("cp.async.commit_group;" ::: "memory");
            asm volatile("cp.async.wait_group 1;" ::: "memory");
        } else {
            asm volatile("cp.async.wait_group 0;" ::: "memory");
        }
        __syncthreads();

        int buf = t & 1;
        unsigned aB = smBase + (unsigned)(buf * 2 * GAB);
        unsigned bB = aB + GAB;
        #pragma unroll
        for (int kk = 0; kk < 64; kk += 16) {
            unsigned af[4][4];
            #pragma unroll
            for (int mi = 0; mi < 4; mi++)
                ldsm4(af[mi], aB + (unsigned)((wm + mi * 16) * GSTR + kk + offL) * 2u);
            #pragma unroll
            for (int g = 0; g < 4; g++) {
                unsigned bf[4];
                ldsm4(bf, bB + (unsigned)((wn + g * 16) * GSTR + kk + offL) * 2u);
                #pragma unroll
                for (int mi = 0; mi < 4; mi++) {
                    mma16(acc[mi][2 * g],     af[mi], bf[0], bf[2]);
                    mma16(acc[mi][2 * g + 1], af[mi], bf[1], bf[3]);
                }
            }
        }
        __syncthreads();
    }

    {
        int q = lane >> 2, r2 = (lane & 3) * 2;
        #pragma unroll
        for (int mi = 0; mi < 4; mi++) {
            int row = row0 + wm + mi * 16 + q;
            #pragma unroll
            for (int ni = 0; ni < 8; ni++) {
                int col = col0 + wn + ni * 8 + r2;
                float v0 = acc[mi][ni][0], v1 = acc[mi][ni][1];
                float v2 = acc[mi][ni][2], v3 = acc[mi][ni][3];
                if (resid) {
                    __half2 r0 = ((const __half2*)resid)[((size_t)row * ldc + col) >> 1];
                    __half2 r1 = ((const __half2*)resid)[((size_t)(row + 8) * ldc + col) >> 1];
                    v0 += __low2float(r0); v1 += __high2float(r0);
                    v2 += __low2float(r1); v3 += __high2float(r1);
                }
                if (OUTH) {
                    __half2* C = (__half2*)Cg;
                    C[((size_t)row * ldc + col) >> 1]       = __floats2half2_rn(v0, v1);
                    C[((size_t)(row + 8) * ldc + col) >> 1] = __floats2half2_rn(v2, v3);
                } else {
                    float* C = (float*)Cg;
                    *(float2*)&C[(size_t)row * ldc + col]       = make_float2(v0, v1);
                    *(float2*)&C[(size_t)(row + 8) * ldc + col] = make_float2(v2, v3);
                }
            }
        }
    }
}

// ---------------------------------------------------------------------------
// Flash attention, register-resident P (round-10 proven).
// ---------------------------------------------------------------------------
#define FSTR 72
#define FKH  9216
#define FVH  18432
#define FKVB 4608
#define FA_SMEM 55296

__global__ __launch_bounds__(256, 2)
void flash_h(const __half* __restrict__ qkv, __half* __restrict__ O, int extraFlag) {
    extern __shared__ __align__(16) char smraw[];
    const int tid = threadIdx.x, lane = tid & 31, warp = tid >> 5;
    const int wm = warp * 16;
    const int qb = blockIdx.x, bh = blockIdx.y;
    const int b = bh >> 4, h = bh & 15;
    const int qrow0 = qb * 128;

    const unsigned smBase = (unsigned)__cvta_generic_to_shared(smraw);
    const int offL = off16(lane, FSTR);
    const int offV = off16v(lane, FSTR);

    const __half* base = qkv + (size_t)(b * SEQ) * 3072 + h * 64;

    {
        const __half* Qsrc = base + (size_t)qrow0 * 3072;
        #pragma unroll
        for (int s = 0; s < 4; s++) {
            int c = tid + 256 * s;
            int m = c >> 3, kc = (c & 7) * 8;
            cp16(smBase + (unsigned)(m * FSTR + kc) * 2u, Qsrc + (size_t)m * 3072 + kc);
        }
    }
    auto loadKV = [&](int t) {
        int buf = t & 1;
        unsigned kB = smBase + (unsigned)(FKH + buf * FKVB) * 2u;
        unsigned vB = smBase + (unsigned)(FVH + buf * FKVB) * 2u;
        const __half* Ksrc = base + (size_t)(t * 64) * 3072 + 1024;
        const __half* Vsrc = base + (size_t)(t * 64) * 3072 + 2048;
        #pragma unroll
        for (int s = 0; s < 2; s++) {
            int c = tid + 256 * s;
            int n = c >> 3, kc = (c & 7) * 8;
            cp16(kB + (unsigned)(n * FSTR + kc) * 2u, Ksrc + (size_t)n * 3072 + kc);
            cp16(vB + (unsigned)(n * FSTR + kc) * 2u, Vsrc + (size_t)n * 3072 + kc);
        }
    };
    loadKV(0);
    asm volatile("cp.async.commit_group;" ::: "memory");

    float m0 = -INFINITY, m1 = -INFINITY, l0 = 0.0f, l1 = 0.0f;
    float oacc[8][4];
    #pragma unroll
    for (int ni = 0; ni < 8; ni++)
        #pragma unroll
        for (int c = 0; c < 4; c++) oacc[ni][c] = 0.0f;

    for (int t = 0; t < 16; t++) {
        if (t + 1 < 16) {
            loadKV(t + 1);
            asm volatile("cp.async.commit_group;" ::: "memory");
            asm volatile("cp.async.wait_group 1;" ::: "memory");
        } else {
            asm volatile("cp.async.wait_group 0;" ::: "memory");
        }
        __syncthreads();

        int buf = t & 1;
        unsigned kB = smBase + (unsigned)(FKH + buf * FKVB) * 2u;
        unsigned vB = smBase + (unsigned)(FVH + buf * FKVB) * 2u;

        float sc[8][4];
        #pragma unroll
        for (int ni = 0; ni < 8; ni++)
            #pragma unroll
            for (int c = 0; c < 4; c++) sc[ni][c] = 0.0f;
        #pragma unroll
        for (int kki = 0; kki < 4; kki++) {
            int kk = kki * 16;
            unsigned af[4];
            ldsm4(af, smBase + (unsigned)(wm * FSTR + kk + offL) * 2u);
            #pragma unroll
            for (int g = 0; g < 4; g++) {
                unsigned bf[4];
                ldsm4(bf, kB + (unsigned)((g * 16) * FSTR + kk + offL) * 2u);
                mma16(sc[2 * g],     af, bf[0], bf[2]);
                mma16(sc[2 * g + 1], af, bf[1], bf[3]);
            }
        }

        float rm0 = -INFINITY, rm1 = -INFINITY;
        #pragma unroll
        for (int ni = 0; ni < 8; ni++) {
            sc[ni][0] *= 0.125f; sc[ni][1] *= 0.125f;
            sc[ni][2] *= 0.125f; sc[ni][3] *= 0.125f;
            rm0 = fmaxf(rm0, fmaxf(sc[ni][0], sc[ni][1]));
            rm1 = fmaxf(rm1, fmaxf(sc[ni][2], sc[ni][3]));
        }
        rm0 = fmaxf(rm0, __shfl_xor_sync(0xffffffff, rm0, 1));
        rm0 = fmaxf(rm0, __shfl_xor_sync(0xffffffff, rm0, 2));
        rm1 = fmaxf(rm1, __shfl_xor_sync(0xffffffff, rm1, 1));
        rm1 = fmaxf(rm1, __shfl_xor_sync(0xffffffff, rm1, 2));
        float nm0 = fmaxf(m0, rm0), nm1 = fmaxf(m1, rm1);
        float c0 = __expf(m0 - nm0), c1 = __expf(m1 - nm1);
        m0 = nm0; m1 = nm1;
        float s0 = 0.0f, s1 = 0.0f;
        bool dbl = extraFlag && (t == 15);
        #pragma unroll
        for (int ni = 0; ni < 8; ni++) {
            float p00 = __expf(sc[ni][0] - nm0);
            float p01 = __expf(sc[ni][1] - nm0);
            float p10 = __expf(sc[ni][2] - nm1);
            float p11 = __expf(sc[ni][3] - nm1);
            if (dbl && ni >= 6) { p00 *= 2.f; p01 *= 2.f; p10 *= 2.f; p11 *= 2.f; }
            s0 += p00 + p01; s1 += p10 + p11;
            sc[ni][0] = p00; sc[ni][1] = p01; sc[ni][2] = p10; sc[ni][3] = p11;
        }
        s0 += __shfl_xor_sync(0xffffffff, s0, 1);
        s0 += __shfl_xor_sync(0xffffffff, s0, 2);
        s1 += __shfl_xor_sync(0xffffffff, s1, 1);
        s1 += __shfl_xor_sync(0xffffffff, s1, 2);
        l0 = l0 * c0 + s0;
        l1 = l1 * c1 + s1;

        #pragma unroll
        for (int ni = 0; ni < 8; ni++) {
            oacc[ni][0] *= c0; oacc[ni][1] *= c0;
            oacc[ni][2] *= c1; oacc[ni][3] *= c1;
        }
        #pragma unroll
        for (int kki = 0; kki < 4; kki++) {
            int ni0 = 2 * kki;
            unsigned af2[4];
            af2[0] = packh2(sc[ni0][0],     sc[ni0][1]);
            af2[1] = packh2(sc[ni0][2],     sc[ni0][3]);
            af2[2] = packh2(sc[ni0 + 1][0], sc[ni0 + 1][1]);
            af2[3] = packh2(sc[ni0 + 1][2], sc[ni0 + 1][3]);
            #pragma unroll
            for (int g = 0; g < 4; g++) {
                unsigned bf[4];
                ldsm4t(bf, vB + (unsigned)((kki * 16) * FSTR + g * 16 + offV) * 2u);
                mma16(oacc[2 * g],     af2, bf[0], bf[2]);
                mma16(oacc[2 * g + 1], af2, bf[1], bf[3]);
            }
        }
        __syncthreads();
    }

    {
        int q = lane >> 2, r2c = (lane & 3) * 2;
        float i0 = 1.0f / l0, i1 = 1.0f / l1;
        int row0 = qrow0 + wm + q;
        #pragma unroll
        for (int ni = 0; ni < 8; ni++) {
            int col = h * 64 + ni * 8 + r2c;
            size_t g0 = (size_t)(b * SEQ + row0) * D_MODEL + col;
            size_t g1 = (size_t)(b * SEQ + row0 + 8) * D_MODEL + col;
            ((__half2*)O)[g0 >> 1] = __floats2half2_rn(oacc[ni][0] * i0, oacc[ni][1] * i0);
            ((__half2*)O)[g1 >> 1] = __floats2half2_rn(oacc[ni][2] * i1, oacc[ni][3] * i1);
        }
    }
}

// ---------------------------------------------------------------------------
// Reductions / LN
// ---------------------------------------------------------------------------
__device__ __forceinline__ float block_reduce_sum(float val, float* sdata) {
    int t = threadIdx.x;
    #pragma unroll
    for (int off = 16; off > 0; off >>= 1)
        val += __shfl_down_sync(0xffffffff, val, off);
    if ((t & 31) == 0) sdata[t >> 5] = val;
    __syncthreads();
    if (t < 32) {
        float v = (t < 8) ? sdata[t] : 0.0f;
        #pragma unroll
        for (int off = 4; off > 0; off >>= 1)
            v += __shfl_down_sync(0xffffffff, v, off);
        if (t == 0) sdata[0] = v;
    }
    __syncthreads();
    float r = sdata[0];
    __syncthreads();
    return r;
}

// LN over fp32 proj; writes fp16 (and/or fp32) out; optional new_mem rows.
__global__ __launch_bounds__(256)
void ln_kernel(const float* __restrict__ x, const float* __restrict__ g,
               const float* __restrict__ bb, float* __restrict__ outf,
               __half* __restrict__ outh, float* __restrict__ memout) {
    __shared__ float sdata[32];
    int row = blockIdx.x;
    int t = threadIdx.x;
    const float* xr = x + (size_t)row * D_MODEL;
    float v[4];
    #pragma unroll
    for (int i = 0; i < 4; i++) v[i] = xr[t + 256 * i];
    float s = v[0] + v[1] + v[2] + v[3];
    float mu = block_reduce_sum(s, sdata) * (1.0f / 1024.0f);
    float sq = 0.f;
    #pragma unroll
    for (int i = 0; i < 4; i++) { float d0 = v[i] - mu; sq += d0 * d0; }
    float var = block_reduce_sum(sq, sdata) * (1.0f / 1024.0f);
    float inv = 1.0f / sqrtf(var + 1e-5f);
    int srow = row & (SEQ - 1), bidx = row >> 10;
    bool isMem = memout && (srow >= 1008);
    float* mrow = isMem ? memout + ((size_t)(bidx * 16 + srow - 1008)) * D_MODEL : nullptr;
    #pragma unroll
    for (int i = 0; i < 4; i++) {
        int c = t + 256 * i;
        float o = (v[i] - mu) * inv * g[c] + bb[c];
        if (outf) outf[(size_t)row * D_MODEL + c] = o;
        if (outh) outh[(size_t)row * D_MODEL + c] = __float2half(o);
        if (isMem) mrow[c] = o;
    }
}

// y = hidsh(fp16) + LN(proj)*g1+b1 ; out_h = fp16(LN(y)*g2+b2)
__global__ __launch_bounds__(256)
void ln_ln_kernel(const float* __restrict__ proj,
                  const float* __restrict__ g1, const float* __restrict__ b1,
                  const __half* __restrict__ hidsh,
                  const float* __restrict__ g2, const float* __restrict__ b2,
                  __half* __restrict__ outh) {
    __shared__ float sdata[32];
    int row = blockIdx.x;
    int t = threadIdx.x;
    const float* xr = proj + (size_t)row * D_MODEL;
    const __half* hr = hidsh + (size_t)row * D_MODEL;
    float v[4], hv[4];
    #pragma unroll
    for (int i = 0; i < 4; i++) { v[i] = xr[t + 256 * i]; hv[i] = __half2float(hr[t + 256 * i]); }
    float s = v[0] + v[1] + v[2] + v[3];
    float mu = block_reduce_sum(s, sdata) * (1.0f / 1024.0f);
    float sq = 0.f;
    #pragma unroll
    for (int i = 0; i < 4; i++) { float d0 = v[i] - mu; sq += d0 * d0; }
    float var = block_reduce_sum(sq, sdata) * (1.0f / 1024.0f);
    float inv = 1.0f / sqrtf(var + 1e-5f);
    float y[4];
    #pragma unroll
    for (int i = 0; i < 4; i++) {
        int c = t + 256 * i;
        y[i] = hv[i] + (v[i] - mu) * inv * g1[c] + b1[c];
    }
    float s2 = y[0] + y[1] + y[2] + y[3];
    float mu2 = block_reduce_sum(s2, sdata) * (1.0f / 1024.0f);
    float sq2 = 0.f;
    #pragma unroll
    for (int i = 0; i < 4; i++) { float d0 = y[i] - mu2; sq2 += d0 * d0; }
    float var2 = block_reduce_sum(sq2, sdata) * (1.0f / 1024.0f);
    float inv2 = 1.0f / sqrtf(var2 + 1e-5f);
    #pragma unroll
    for (int i = 0; i < 4; i++) {
        int c = t + 256 * i;
        float o = (y[i] - mu2) * inv2 * g2[c] + b2[c];
        outh[(size_t)row * D_MODEL + c] = __float2half(o);
    }
}

// ---------------------------------------------------------------------------
static float *s_proj = 0, *s_pos = 0;
static __half *s_h0h = 0, *s_qkvh = 0, *s_attnh = 0, *s_hidsh = 0, *s_outh = 0;
static __half *s_wTa = 0, *s_wTo = 0, *s_wTaow = 0, *s_wToow = 0, *s_wTff2 = 0;

static void resolve_scratch() {
    if (s_proj) return;
    cudaGetSymbolAddress((void**)&s_proj,  g_proj);
    cudaGetSymbolAddress((void**)&s_pos,   g_pos);
    cudaGetSymbolAddress((void**)&s_h0h,   g_h0h);
    cudaGetSymbolAddress((void**)&s_qkvh,  g_qkvh);
    cudaGetSymbolAddress((void**)&s_attnh, g_attnh);
    cudaGetSymbolAddress((void**)&s_hidsh, g_hidsh);
    cudaGetSymbolAddress((void**)&s_outh,  g_outh);
    cudaGetSymbolAddress((void**)&s_wTa,   g_wTa);
    cudaGetSymbolAddress((void**)&s_wTo,   g_wTo);
    cudaGetSymbolAddress((void**)&s_wTaow, g_wTaow);
    cudaGetSymbolAddress((void**)&s_wToow, g_wToow);
    cudaGetSymbolAddress((void**)&s_wTff2, g_wTff2);
    cudaFuncSetAttribute(gemm_h<false>, cudaFuncAttributeMaxDynamicSharedMemorySize, GSMEM);
    cudaFuncSetAttribute(gemm_h<true>,  cudaFuncAttributeMaxDynamicSharedMemorySize, GSMEM);
    cudaFuncSetAttribute(flash_h, cudaFuncAttributeMaxDynamicSharedMemorySize, FA_SMEM);
}

static void run_attention(const __half* xh, const __half* wT, int extraFlag) {
    gemm_h<true><<<dim3(24, 32), 128, GSMEM>>>(
        xh, wT, nullptr, s_qkvh, 1024, 1024, 1024, 3072);
    flash_h<<<dim3(8, BATCH * NHEAD), 256, FA_SMEM>>>(s_qkvh, s_attnh, extraFlag);
}

extern "C" void kernel_launch(void* const* d_in, const int* in_sizes, int n_in,
                              void* d_out, int out_size) {
    const int*   data  = (const int*)d_in[0];
    const float* emb   = (const float*)d_in[2];
    const float* a_qw  = (const float*)d_in[3];
    const float* a_kvw = (const float*)d_in[4];
    const float* a_ow  = (const float*)d_in[5];
    const float* a_g   = (const float*)d_in[6];
    const float* a_b   = (const float*)d_in[7];
    const float* o_qw  = (const float*)d_in[16];
    const float* o_kvw = (const float*)d_in[17];
    const float* o_ow  = (const float*)d_in[18];
    const float* o_g   = (const float*)d_in[19];
    const float* o_b   = (const float*)d_in[20];
    const float* ff2_w = (const float*)d_in[21];
    const float* ln1_g = (const float*)d_in[22];
    const float* ln1_b = (const float*)d_in[23];
    const float* ln2_g = (const float*)d_in[24];
    const float* ln2_b = (const float*)d_in[25];
    float* out = (float*)d_out;

    resolve_scratch();

    TpArgs tp;
    tp.src[0] = a_qw;          tp.dst[0] = s_wTa;               tp.ld[0] = 1024;
    tp.src[1] = a_kvw;         tp.dst[1] = s_wTa + 1024*1024;   tp.ld[1] = 2048;
    tp.src[2] = a_kvw + 1024;  tp.dst[2] = s_wTa + 2*1024*1024; tp.ld[2] = 2048;
    tp.src[3] = o_qw;          tp.dst[3] = s_wTo;               tp.ld[3] = 1024;
    tp.src[4] = o_kvw;         tp.dst[4] = s_wTo + 1024*1024;   tp.ld[4] = 2048;
    tp.src[5] = o_kvw + 1024;  tp.dst[5] = s_wTo + 2*1024*1024; tp.ld[5] = 2048;
    tp.src[6] = a_ow;          tp.dst[6] = s_wTaow;             tp.ld[6] = 1024;
    tp.src[7] = o_ow;          tp.dst[7] = s_wToow;             tp.ld[7] = 1024;
    tp.src[8] = ff2_w;         tp.dst[8] = s_wTff2;             tp.ld[8] = 1024;
    transpose_h_kernel<<<dim3(32, 32, 9), dim3(32, 8)>>>(tp);

    pos_kernel<<<(SEQ * D_MODEL) / 256, 256>>>(s_pos);
    embed_kernel<<<OUT_MAIN / 256, 256>>>(data, emb, s_pos, s_h0h);

    // self attention (layer); residual = h0h (fp16)
    run_attention(s_h0h, s_wTa, 0);
    gemm_h<false><<<dim3(8, 32), 128, GSMEM>>>(
        s_attnh, s_wTaow, s_h0h, s_proj, 1024, 1024, 1024, 1024);
    // LN -> hidsh (fp16) + new_mem rows (fp32, from fp32 LN math)
    ln_kernel<<<MROWS, 256>>>(s_proj, a_g, a_b, nullptr, s_hidsh, out + OUT_MAIN);

    // OutputAttn (keys >= 1008 double-weighted); residual = hidsh (fp16)
    run_attention(s_hidsh, s_wTo, 1);
    gemm_h<false><<<dim3(8, 32), 128, GSMEM>>>(
        s_attnh, s_wToow, s_hidsh, s_proj, 1024, 1024, 1024, 1024);
    ln_ln_kernel<<<MROWS, 256>>>(s_proj, o_g, o_b, s_hidsh, ln1_g, ln1_b, s_outh);

    // output = LN(outh @ ff2 + outh, ln2); residual = outh (fp16)
    gemm_h<false><<<dim3(8, 32), 128, GSMEM>>>(
        s_outh, s_wTff2, s_outh, s_proj, 1024, 1024, 1024, 1024);
    ln_kernel<<<MROWS, 256>>>(s_proj, ln2_g, ln2_b, out, nullptr, nullptr);
}

// round 14
// speedup vs baseline: 1.0422x; 1.0337x over previous
#include <cuda_runtime.h>
#include <cuda_fp16.h>
#include <math.h>

// ---------------------------------------------------------------------------
// MemTransformerLMEncoder - fp16 mma.sync; mbarrier-pipelined flash attention
// (no block barriers in mainloop -> warp skew overlaps softmax with HMMA).
// Dead code: UpdateAttn branch + mem input unused. new_mem = hids[:,1008:1024].
// OutputAttn = 1024-key softmax with keys >=1008 double-weighted.
// GEMM at ~95% of legacy-HMMA issue ceiling (~272 TF/s); tcgen05 blocked by
// harness compute_103 virtual arch.
// ---------------------------------------------------------------------------

#define D_MODEL 1024
#define SEQ     1024
#define BATCH   4
#define NHEAD   16
#define DHEAD   64
#define MROWS   (BATCH*SEQ)            // 4096
#define OUT_MAIN (BATCH*SEQ*D_MODEL)   // 4194304

// fp32 scratch
__device__ float g_proj[MROWS*D_MODEL];
__device__ float g_pos[SEQ*D_MODEL];
// fp16 scratch
__device__ __half g_h0h[MROWS*D_MODEL];
__device__ __half g_qkvh[MROWS*3*D_MODEL];
__device__ __half g_attnh[MROWS*D_MODEL];
__device__ __half g_hidsh[MROWS*D_MODEL];
__device__ __half g_outh[MROWS*D_MODEL];
// fp16 transposed weights
__device__ __half g_wTa[3*D_MODEL*D_MODEL];
__device__ __half g_wTo[3*D_MODEL*D_MODEL];
__device__ __half g_wTaow[D_MODEL*D_MODEL];
__device__ __half g_wToow[D_MODEL*D_MODEL];
__device__ __half g_wTff2[D_MODEL*D_MODEL];

// ---------------------------------------------------------------------------
__device__ __forceinline__ void mma16(float* c, const unsigned* a, unsigned b0, unsigned b1) {
    asm volatile(
        "mma.sync.aligned.m16n8k16.row.col.f32.f16.f16.f32 "
        "{%0,%1,%2,%3}, {%4,%5,%6,%7}, {%8,%9}, {%0,%1,%2,%3};"
        : "+f"(c[0]), "+f"(c[1]), "+f"(c[2]), "+f"(c[3])
        : "r"(a[0]), "r"(a[1]), "r"(a[2]), "r"(a[3]), "r"(b0), "r"(b1));
}
__device__ __forceinline__ void ldsm4(unsigned* r, unsigned addr) {
    asm volatile("ldmatrix.sync.aligned.m8n8.x4.shared.b16 {%0,%1,%2,%3}, [%4];"
        : "=r"(r[0]), "=r"(r[1]), "=r"(r[2]), "=r"(r[3]) : "r"(addr));
}
__device__ __forceinline__ void ldsm4t(unsigned* r, unsigned addr) {
    asm volatile("ldmatrix.sync.aligned.m8n8.x4.trans.shared.b16 {%0,%1,%2,%3}, [%4];"
        : "=r"(r[0]), "=r"(r[1]), "=r"(r[2]), "=r"(r[3]) : "r"(addr));
}
__device__ __forceinline__ void cp16(unsigned dst, const void* src) {
    asm volatile("cp.async.cg.shared.global [%0], [%1], 16;" :: "r"(dst), "l"(src));
}
__device__ __forceinline__ int off16(int lane, int STR) {
    return ((lane & 7) + ((lane >> 3) & 1) * 8) * STR + ((lane >> 4) & 1) * 8;
}
__device__ __forceinline__ int off16v(int lane, int STR) {
    return ((lane & 7) + ((lane >> 4) & 1) * 8) * STR + ((lane >> 3) & 1) * 8;
}
__device__ __forceinline__ unsigned packh2(float a, float b) {
    __half2 h = __floats2half2_rn(a, b);
    return *(unsigned*)&h;
}

#define MBAR_INIT(addr, cnt) \
    asm volatile("mbarrier.init.shared.b64 [%0], %1;" :: "r"(addr), "r"((unsigned)(cnt)) : "memory")
#define MBAR_ARRIVE(addr) \
    asm volatile("mbarrier.arrive.shared.b64 _, [%0];" :: "r"(addr) : "memory")
#define CP_ASYNC_MBAR_ARRIVE(addr) \
    asm volatile("cp.async.mbarrier.arrive.noinc.shared::cta.b64 [%0];" :: "r"(addr) : "memory")
#define MBAR_WAIT(mbar_addr, phase_parity) do { \
    unsigned _mb = (mbar_addr); \
    unsigned _ph = (phase_parity); \
    unsigned _done; \
    asm volatile( \
        "{\n\t.reg .pred p;\n\t" \
        "mbarrier.try_wait.parity.acquire.cta.shared::cta.b64 p, [%1], %2;\n\t" \
        "selp.b32 %0, 1, 0, p;\n\t}" \
        : "=r"(_done) : "r"(_mb), "r"(_ph) : "memory"); \
    if (!_done) { \
        asm volatile( \
            "{\n\t.reg .pred P1;\n\t" \
            "WL_%=:\n\t" \
            "mbarrier.try_wait.parity.acquire.cta.shared::cta.b64 P1, [%0], %1, 0x989680;\n\t" \
            "@P1 bra.uni WD_%=;\n\t" \
            "bra.uni WL_%=;\n\t" \
            "WD_%=:\n\t}" \
            :: "r"(_mb), "r"(_ph) : "memory"); \
    } \
} while (0)

// ---------------------------------------------------------------------------
// Positional table (depends only on s,d).
// ---------------------------------------------------------------------------
__global__ void pos_kernel(float* __restrict__ pos) {
    int idx = blockIdx.x * 256 + threadIdx.x;
    int d = idx & (D_MODEL - 1);
    int s = idx >> 10;
    float freq  = powf(10000.0f, -(float)(d & ~1) * (1.0f / 1024.0f));
    float angle = (float)s * freq;
    pos[idx] = (d & 1) ? cosf(angle) : sinf(angle);
}

__global__ void embed_kernel(const int* __restrict__ data,
                             const float* __restrict__ emb,
                             const float* __restrict__ pos,
                             __half* __restrict__ outh) {
    int idx = blockIdx.x * 256 + threadIdx.x;
    int d  = idx & (D_MODEL - 1);
    int bs = idx >> 10;
    int s  = bs & (SEQ - 1);
    int tok = data[bs];
    float v = emb[(size_t)tok * D_MODEL + d] * 32.0f + pos[(s << 10) + d];
    outh[idx] = __float2half(v);
}

// ---------------------------------------------------------------------------
// Fused transpose+fp16 convert: 9 units of 1024x1024
// ---------------------------------------------------------------------------
struct TpArgs {
    const float* src[9];
    __half* dst[9];
    int ld[9];
};
__global__ void transpose_h_kernel(TpArgs a) {
    __shared__ float tile[32][33];
    int u = blockIdx.z;
    const float* src = a.src[u];
    __half* dst = a.dst[u];
    int ld = a.ld[u];
    int kb = blockIdx.y * 32, nb = blockIdx.x * 32;
    int tx = threadIdx.x, ty = threadIdx.y;
    #pragma unroll
    for (int i = 0; i < 32; i += 8)
        tile[ty + i][tx] = src[(size_t)(kb + ty + i) * ld + nb + tx];
    __syncthreads();
    #pragma unroll
    for (int i = 0; i < 32; i += 8)
        dst[(size_t)(nb + ty + i) * 1024 + kb + tx] = __float2half(tile[tx][ty + i]);
}

// ---------------------------------------------------------------------------
// fp16 GEMM (round-11/12 proven): 4 warps, 64x64 warp tiles, CTA 128x128,
// BK=64, 2-stage cp.async. C = A[M,K] @ B[N,K]^T (+fp16 resid).
// ---------------------------------------------------------------------------
#define GSTR 72
#define GAB  (128*GSTR*2)               // 18432 bytes per buffer
#define GSMEM (2*2*GAB)                 // 73728

template<bool OUTH>
__global__ __launch_bounds__(128, 2)
void gemm_h(const __half* __restrict__ A, const __half* __restrict__ B,
            const __half* __restrict__ resid, void* __restrict__ Cg,
            int K, int lda, int ldb, int ldc) {
    extern __shared__ __align__(16) char smraw[];
    const int tid = threadIdx.x, lane = tid & 31, warp = tid >> 5;
    const int row0 = blockIdx.y * 128, col0 = blockIdx.x * 128;
    const int wm = (warp & 1) * 64, wn = (warp >> 1) * 64;
    const unsigned smBase = (unsigned)__cvta_generic_to_shared(smraw);
    const int offL = off16(lane, GSTR);

    float acc[4][8][4];
    #pragma unroll
    for (int mi = 0; mi < 4; mi++)
        #pragma unroll
        for (int ni = 0; ni < 8; ni++)
            #pragma unroll
            for (int c = 0; c < 4; c++) acc[mi][ni][c] = 0.0f;

    const int T = K / 64;

    auto loadTile = [&](int t) {
        int buf = t & 1;
        unsigned aB = smBase + (unsigned)(buf * 2 * GAB);
        unsigned bB = aB + GAB;
        const __half* Asrc = A + (size_t)row0 * lda + t * 64;
        const __half* Bsrc = B + (size_t)col0 * ldb + t * 64;
        #pragma unroll
        for (int s = 0; s < 8; s++) {
            int c = tid + 128 * s;
            int m = c >> 3, kc = (c & 7) * 8;
            cp16(aB + (unsigned)(m * GSTR + kc) * 2u, Asrc + (size_t)m * lda + kc);
        }
        #pragma unroll
        for (int s = 0; s < 8; s++) {
            int c = tid + 128 * s;
            int n = c >> 3, kc = (c & 7) * 8;
            cp16(bB + (unsigned)(n * GSTR + kc) * 2u, Bsrc + (size_t)n * ldb + kc);
        }
    };

    loadTile(0);
    asm volatile("cp.async.commit_group;" ::: "memory");

    for (int t = 0; t < T; t++) {
        if (t + 1 < T) {
            loadTile(t + 1);
            asm volatile("cp.async.commit_group;" ::: "memory");
            asm volatile("cp.async.wait_group 1;" ::: "memory");
        } else {
            asm volatile("cp.async.wait_group 0;" ::: "memory");
        }
        __syncthreads();

        int buf = t & 1;
        unsigned aB = smBase + (unsigned)(buf * 2 * GAB);
        unsigned bB = aB + GAB;
        #pragma unroll
        for (int kk = 0; kk < 64; kk += 16) {
            unsigned af[4][4];
            #pragma unroll
            for (int mi = 0; mi < 4; mi++)
                ldsm4(af[mi], aB + (unsigned)((wm + mi * 16) * GSTR + kk + offL) * 2u);
            #pragma unroll
            for (int g = 0; g < 4; g++) {
                unsigned bf[4];
                ldsm4(bf, bB + (unsigned)((wn + g * 16) * GSTR + kk + offL) * 2u);
                #pragma unroll
                for (int mi = 0; mi < 4; mi++) {
                    mma16(acc[mi][2 * g],     af[mi], bf[0], bf[2]);
                    mma16(acc[mi][2 * g + 1], af[mi], bf[1], bf[3]);
                }
            }
        }
        __syncthreads();
    }

    {
        int q = lane >> 2, r2 = (lane & 3) * 2;
        #pragma unroll
        for (int mi = 0; mi < 4; mi++) {
            int row = row0 + wm + mi * 16 + q;
            #pragma unroll
            for (int ni = 0; ni < 8; ni++) {
                int col = col0 + wn + ni * 8 + r2;
                float v0 = acc[mi][ni][0], v1 = acc[mi][ni][1];
                float v2 = acc[mi][ni][2], v3 = acc[mi][ni][3];
                if (resid) {
                    __half2 r0 = ((const __half2*)resid)[((size_t)row * ldc + col) >> 1];
                    __half2 r1 = ((const __half2*)resid)[((size_t)(row + 8) * ldc + col) >> 1];
                    v0 += __low2float(r0); v1 += __high2float(r0);
                    v2 += __low2float(r1); v3 += __high2float(r1);
                }
                if (OUTH) {
                    __half2* C = (__half2*)Cg;
                    C[((size_t)row * ldc + col) >> 1]       = __floats2half2_rn(v0, v1);
                    C[((size_t)(row + 8) * ldc + col) >> 1] = __floats2half2_rn(v2, v3);
                } else {
                    float* C = (float*)Cg;
                    *(float2*)&C[(size_t)row * ldc + col]       = make_float2(v0, v1);
                    *(float2*)&C[(size_t)(row + 8) * ldc + col] = make_float2(v2, v3);
                }
            }
        }
    }
}

// ---------------------------------------------------------------------------
// Flash attention, register-resident P, mbarrier-pipelined KV (4-deep ring,
// prefetch distance 2, NO block barriers in the mainloop).
// grid=(SEQ/128, B*H), 256 thr; warp w owns 16 query rows x all 64 keys.
// full[s]: count 256, cp.async.mbarrier.arrive.noinc per thread.
// empty[s]: count 8, lane-0 arrive per warp after consuming.
// Parity schedule (verified): consumer (t>>2)&1; producer ((pf>>2)+1)&1,
// prologue loads tiles 0,1 without waits (their first-pass is consumed).
// ---------------------------------------------------------------------------
#define FSTR 72
#define FQ_HALVES (128*FSTR)            // 9216
#define FKVB 4608                        // halves per K (or V) buffer
#define KBUF(s) (FQ_HALVES + (s)*FKVB)
#define VBUF(s) (FQ_HALVES + 4*FKVB + (s)*FKVB)
#define FMB_OFF 92160                    // bytes: (9216 + 8*4608)*2
#define FA_SMEM (FMB_OFF + 64)           // 92224

__global__ __launch_bounds__(256, 2)
void flash_h(const __half* __restrict__ qkv, __half* __restrict__ O, int extraFlag) {
    extern __shared__ __align__(16) char smraw[];
    const int tid = threadIdx.x, lane = tid & 31, warp = tid >> 5;
    const int wm = warp * 16;
    const int qb = blockIdx.x, bh = blockIdx.y;
    const int b = bh >> 4, h = bh & 15;
    const int qrow0 = qb * 128;

    const unsigned smBase = (unsigned)__cvta_generic_to_shared(smraw);
    const unsigned mbF = smBase + FMB_OFF;        // full[0..3] at +0,8,16,24
    const unsigned mbE = smBase + FMB_OFF + 32;   // empty[0..3]
    const int offL = off16(lane, FSTR);
    const int offV = off16v(lane, FSTR);

    if (tid == 0) {
        #pragma unroll
        for (int s = 0; s < 4; s++) {
            MBAR_INIT(mbF + 8u * s, 256);
            MBAR_INIT(mbE + 8u * s, 8);
        }
    }
    __syncthreads();

    const __half* base = qkv + (size_t)(b * SEQ) * 3072 + h * 64;

    auto loadKV = [&](int t, int s) {
        unsigned kB = smBase + (unsigned)KBUF(s) * 2u;
        unsigned vB = smBase + (unsigned)VBUF(s) * 2u;
        const __half* Ksrc = base + (size_t)(t * 64) * 3072 + 1024;
        const __half* Vsrc = base + (size_t)(t * 64) * 3072 + 2048;
        #pragma unroll
        for (int si = 0; si < 2; si++) {
            int c = tid + 256 * si;
            int n = c >> 3, kc = (c & 7) * 8;
            cp16(kB + (unsigned)(n * FSTR + kc) * 2u, Ksrc + (size_t)n * 3072 + kc);
            cp16(vB + (unsigned)(n * FSTR + kc) * 2u, Vsrc + (size_t)n * 3072 + kc);
        }
    };

    // prologue: Q + KV tiles 0,1
    {
        const __half* Qsrc = base + (size_t)qrow0 * 3072;
        #pragma unroll
        for (int s = 0; s < 4; s++) {
            int c = tid + 256 * s;
            int m = c >> 3, kc = (c & 7) * 8;
            cp16(smBase + (unsigned)(m * FSTR + kc) * 2u, Qsrc + (size_t)m * 3072 + kc);
        }
    }
    loadKV(0, 0);
    CP_ASYNC_MBAR_ARRIVE(mbF + 0u);
    loadKV(1, 1);
    CP_ASYNC_MBAR_ARRIVE(mbF + 8u);
    // make Q visible to all warps (waits this thread's cp.asyncs, then barrier)
    asm volatile("cp.async.commit_group;" ::: "memory");
    asm volatile("cp.async.wait_group 0;" ::: "memory");
    __syncthreads();

    float m0 = -INFINITY, m1 = -INFINITY, l0 = 0.0f, l1 = 0.0f;
    float oacc[8][4];
    #pragma unroll
    for (int ni = 0; ni < 8; ni++)
        #pragma unroll
        for (int c = 0; c < 4; c++) oacc[ni][c] = 0.0f;

    for (int t = 0; t < 16; t++) {
        // producer: prefetch tile t+2
        int pf = t + 2;
        if (pf < 16) {
            int s2 = pf & 3;
            MBAR_WAIT(mbE + 8u * s2, ((pf >> 2) + 1) & 1);
            loadKV(pf, s2);
            CP_ASYNC_MBAR_ARRIVE(mbF + 8u * s2);
        }
        // consumer: tile t
        int s = t & 3;
        MBAR_WAIT(mbF + 8u * s, (t >> 2) & 1);
        unsigned kB = smBase + (unsigned)KBUF(s) * 2u;
        unsigned vB = smBase + (unsigned)VBUF(s) * 2u;

        float sc[8][4];
        #pragma unroll
        for (int ni = 0; ni < 8; ni++)
            #pragma unroll
            for (int c = 0; c < 4; c++) sc[ni][c] = 0.0f;
        #pragma unroll
        for (int kki = 0; kki < 4; kki++) {
            int kk = kki * 16;
            unsigned af[4];
            ldsm4(af, smBase + (unsigned)(wm * FSTR + kk + offL) * 2u);
            #pragma unroll
            for (int g = 0; g < 4; g++) {
                unsigned bf[4];
                ldsm4(bf, kB + (unsigned)((g * 16) * FSTR + kk + offL) * 2u);
                mma16(sc[2 * g],     af, bf[0], bf[2]);
                mma16(sc[2 * g + 1], af, bf[1], bf[3]);
            }
        }

        float rm0 = -INFINITY, rm1 = -INFINITY;
        #pragma unroll
        for (int ni = 0; ni < 8; ni++) {
            sc[ni][0] *= 0.125f; sc[ni][1] *= 0.125f;
            sc[ni][2] *= 0.125f; sc[ni][3] *= 0.125f;
            rm0 = fmaxf(rm0, fmaxf(sc[ni][0], sc[ni][1]));
            rm1 = fmaxf(rm1, fmaxf(sc[ni][2], sc[ni][3]));
        }
        rm0 = fmaxf(rm0, __shfl_xor_sync(0xffffffff, rm0, 1));
        rm0 = fmaxf(rm0, __shfl_xor_sync(0xffffffff, rm0, 2));
        rm1 = fmaxf(rm1, __shfl_xor_sync(0xffffffff, rm1, 1));
        rm1 = fmaxf(rm1, __shfl_xor_sync(0xffffffff, rm1, 2));
        float nm0 = fmaxf(m0, rm0), nm1 = fmaxf(m1, rm1);
        float c0 = __expf(m0 - nm0), c1 = __expf(m1 - nm1);
        m0 = nm0; m1 = nm1;
        float s0 = 0.0f, s1 = 0.0f;
        bool dbl = extraFlag && (t == 15);
        #pragma unroll
        for (int ni = 0; ni < 8; ni++) {
            float p00 = __expf(sc[ni][0] - nm0);
            float p01 = __expf(sc[ni][1] - nm0);
            float p10 = __expf(sc[ni][2] - nm1);
            float p11 = __expf(sc[ni][3] - nm1);
            if (dbl && ni >= 6) { p00 *= 2.f; p01 *= 2.f; p10 *= 2.f; p11 *= 2.f; }
            s0 += p00 + p01; s1 += p10 + p11;
            sc[ni][0] = p00; sc[ni][1] = p01; sc[ni][2] = p10; sc[ni][3] = p11;
        }
        s0 += __shfl_xor_sync(0xffffffff, s0, 1);
        s0 += __shfl_xor_sync(0xffffffff, s0, 2);
        s1 += __shfl_xor_sync(0xffffffff, s1, 1);
        s1 += __shfl_xor_sync(0xffffffff, s1, 2);
        l0 = l0 * c0 + s0;
        l1 = l1 * c1 + s1;

        #pragma unroll
        for (int ni = 0; ni < 8; ni++) {
            oacc[ni][0] *= c0; oacc[ni][1] *= c0;
            oacc[ni][2] *= c1; oacc[ni][3] *= c1;
        }
        #pragma unroll
        for (int kki = 0; kki < 4; kki++) {
            int ni0 = 2 * kki;
            unsigned af2[4];
            af2[0] = packh2(sc[ni0][0],     sc[ni0][1]);
            af2[1] = packh2(sc[ni0][2],     sc[ni0][3]);
            af2[2] = packh2(sc[ni0 + 1][0], sc[ni0 + 1][1]);
            af2[3] = packh2(sc[ni0 + 1][2], sc[ni0 + 1][3]);
            #pragma unroll
            for (int g = 0; g < 4; g++) {
                unsigned bf[4];
                ldsm4t(bf, vB + (unsigned)((kki * 16) * FSTR + g * 16 + offV) * 2u);
                mma16(oacc[2 * g],     af2, bf[0], bf[2]);
                mma16(oacc[2 * g + 1], af2, bf[1], bf[3]);
            }
        }
        // warp done with buffer s (ldmatrix reads complete in program order)
        if (lane == 0) MBAR_ARRIVE(mbE + 8u * s);
    }

    {
        int q = lane >> 2, r2c = (lane & 3) * 2;
        float i0 = 1.0f / l0, i1 = 1.0f / l1;
        int row0 = qrow0 + wm + q;
        #pragma unroll
        for (int ni = 0; ni < 8; ni++) {
            int col = h * 64 + ni * 8 + r2c;
            size_t g0 = (size_t)(b * SEQ + row0) * D_MODEL + col;
            size_t g1 = (size_t)(b * SEQ + row0 + 8) * D_MODEL + col;
            ((__half2*)O)[g0 >> 1] = __floats2half2_rn(oacc[ni][0] * i0, oacc[ni][1] * i0);
            ((__half2*)O)[g1 >> 1] = __floats2half2_rn(oacc[ni][2] * i1, oacc[ni][3] * i1);
        }
    }
}

// ---------------------------------------------------------------------------
// Reductions / LN
// ---------------------------------------------------------------------------
__device__ __forceinline__ float block_reduce_sum(float val, float* sdata) {
    int t = threadIdx.x;
    #pragma unroll
    for (int off = 16; off > 0; off >>= 1)
        val += __shfl_down_sync(0xffffffff, val, off);
    if ((t & 31) == 0) sdata[t >> 5] = val;
    __syncthreads();
    if (t < 32) {
        float v = (t < 8) ? sdata[t] : 0.0f;
        #pragma unroll
        for (int off = 4; off > 0; off >>= 1)
            v += __shfl_down_sync(0xffffffff, v, off);
        if (t == 0) sdata[0] = v;
    }
    __syncthreads();
    float r = sdata[0];
    __syncthreads();
    return r;
}

__global__ __launch_bounds__(256)
void ln_kernel(const float* __restrict__ x, const float* __restrict__ g,
               const float* __restrict__ bb, float* __restrict__ outf,
               __half* __restrict__ outh, float* __restrict__ memout) {
    __shared__ float sdata[32];
    int row = blockIdx.x;
    int t = threadIdx.x;
    const float* xr = x + (size_t)row * D_MODEL;
    float v[4];
    #pragma unroll
    for (int i = 0; i < 4; i++) v[i] = xr[t + 256 * i];
    float s = v[0] + v[1] + v[2] + v[3];
    float mu = block_reduce_sum(s, sdata) * (1.0f / 1024.0f);
    float sq = 0.f;
    #pragma unroll
    for (int i = 0; i < 4; i++) { float d0 = v[i] - mu; sq += d0 * d0; }
    float var = block_reduce_sum(sq, sdata) * (1.0f / 1024.0f);
    float inv = 1.0f / sqrtf(var + 1e-5f);
    int srow = row & (SEQ - 1), bidx = row >> 10;
    bool isMem = memout && (srow >= 1008);
    float* mrow = isMem ? memout + ((size_t)(bidx * 16 + srow - 1008)) * D_MODEL : nullptr;
    #pragma unroll
    for (int i = 0; i < 4; i++) {
        int c = t + 256 * i;
        float o = (v[i] - mu) * inv * g[c] + bb[c];
        if (outf) outf[(size_t)row * D_MODEL + c] = o;
        if (outh) outh[(size_t)row * D_MODEL + c] = __float2half(o);
        if (isMem) mrow[c] = o;
    }
}

__global__ __launch_bounds__(256)
void ln_ln_kernel(const float* __restrict__ proj,
                  const float* __restrict__ g1, const float* __restrict__ b1,
                  const __half* __restrict__ hidsh,
                  const float* __restrict__ g2, const float* __restrict__ b2,
                  __half* __restrict__ outh) {
    __shared__ float sdata[32];
    int row = blockIdx.x;
    int t = threadIdx.x;
    const float* xr = proj + (size_t)row * D_MODEL;
    const __half* hr = hidsh + (size_t)row * D_MODEL;
    float v[4], hv[4];
    #pragma unroll
    for (int i = 0; i < 4; i++) { v[i] = xr[t + 256 * i]; hv[i] = __half2float(hr[t + 256 * i]); }
    float s = v[0] + v[1] + v[2] + v[3];
    float mu = block_reduce_sum(s, sdata) * (1.0f / 1024.0f);
    float sq = 0.f;
    #pragma unroll
    for (int i = 0; i < 4; i++) { float d0 = v[i] - mu; sq += d0 * d0; }
    float var = block_reduce_sum(sq, sdata) * (1.0f / 1024.0f);
    float inv = 1.0f / sqrtf(var + 1e-5f);
    float y[4];
    #pragma unroll
    for (int i = 0; i < 4; i++) {
        int c = t + 256 * i;
        y[i] = hv[i] + (v[i] - mu) * inv * g1[c] + b1[c];
    }
    float s2 = y[0] + y[1] + y[2] + y[3];
    float mu2 = block_reduce_sum(s2, sdata) * (1.0f / 1024.0f);
    float sq2 = 0.f;
    #pragma unroll
    for (int i = 0; i < 4; i++) { float d0 = y[i] - mu2; sq2 += d0 * d0; }
    float var2 = block_reduce_sum(sq2, sdata) * (1.0f / 1024.0f);
    float inv2 = 1.0f / sqrtf(var2 + 1e-5f);
    #pragma unroll
    for (int i = 0; i < 4; i++) {
        int c = t + 256 * i;
        float o = (y[i] - mu2) * inv2 * g2[c] + b2[c];
        outh[(size_t)row * D_MODEL + c] = __float2half(o);
    }
}

// ---------------------------------------------------------------------------
static float *s_proj = 0, *s_pos = 0;
static __half *s_h0h = 0, *s_qkvh = 0, *s_attnh = 0, *s_hidsh = 0, *s_outh = 0;
static __half *s_wTa = 0, *s_wTo = 0, *s_wTaow = 0, *s_wToow = 0, *s_wTff2 = 0;

static void resolve_scratch() {
    if (s_proj) return;
    cudaGetSymbolAddress((void**)&s_proj,  g_proj);
    cudaGetSymbolAddress((void**)&s_pos,   g_pos);
    cudaGetSymbolAddress((void**)&s_h0h,   g_h0h);
    cudaGetSymbolAddress((void**)&s_qkvh,  g_qkvh);
    cudaGetSymbolAddress((void**)&s_attnh, g_attnh);
    cudaGetSymbolAddress((void**)&s_hidsh, g_hidsh);
    cudaGetSymbolAddress((void**)&s_outh,  g_outh);
    cudaGetSymbolAddress((void**)&s_wTa,   g_wTa);
    cudaGetSymbolAddress((void**)&s_wTo,   g_wTo);
    cudaGetSymbolAddress((void**)&s_wTaow, g_wTaow);
    cudaGetSymbolAddress((void**)&s_wToow, g_wToow);
    cudaGetSymbolAddress((void**)&s_wTff2, g_wTff2);
    cudaFuncSetAttribute(gemm_h<false>, cudaFuncAttributeMaxDynamicSharedMemorySize, GSMEM);
    cudaFuncSetAttribute(gemm_h<true>,  cudaFuncAttributeMaxDynamicSharedMemorySize, GSMEM);
    cudaFuncSetAttribute(flash_h, cudaFuncAttributeMaxDynamicSharedMemorySize, FA_SMEM);
}

static void run_attention(const __half* xh, const __half* wT, int extraFlag) {
    gemm_h<true><<<dim3(24, 32), 128, GSMEM>>>(
        xh, wT, nullptr, s_qkvh, 1024, 1024, 1024, 3072);
    flash_h<<<dim3(8, BATCH * NHEAD), 256, FA_SMEM>>>(s_qkvh, s_attnh, extraFlag);
}

extern "C" void kernel_launch(void* const* d_in, const int* in_sizes, int n_in,
                              void* d_out, int out_size) {
    const int*   data  = (const int*)d_in[0];
    const float* emb   = (const float*)d_in[2];
    const float* a_qw  = (const float*)d_in[3];
    const float* a_kvw = (const float*)d_in[4];
    const float* a_ow  = (const float*)d_in[5];
    const float* a_g   = (const float*)d_in[6];
    const float* a_b   = (const float*)d_in[7];
    const float* o_qw  = (const float*)d_in[16];
    const float* o_kvw = (const float*)d_in[17];
    const float* o_ow  = (const float*)d_in[18];
    const float* o_g   = (const float*)d_in[19];
    const float* o_b   = (const float*)d_in[20];
    const float* ff2_w = (const float*)d_in[21];
    const float* ln1_g = (const float*)d_in[22];
    const float* ln1_b = (const float*)d_in[23];
    const float* ln2_g = (const float*)d_in[24];
    const float* ln2_b = (const float*)d_in[25];
    float* out = (float*)d_out;

    resolve_scratch();

    TpArgs tp;
    tp.src[0] = a_qw;          tp.dst[0] = s_wTa;               tp.ld[0] = 1024;
    tp.src[1] = a_kvw;         tp.dst[1] = s_wTa + 1024*1024;   tp.ld[1] = 2048;
    tp.src[2] = a_kvw + 1024;  tp.dst[2] = s_wTa + 2*1024*1024; tp.ld[2] = 2048;
    tp.src[3] = o_qw;          tp.dst[3] = s_wTo;               tp.ld[3] = 1024;
    tp.src[4] = o_kvw;         tp.dst[4] = s_wTo + 1024*1024;   tp.ld[4] = 2048;
    tp.src[5] = o_kvw + 1024;  tp.dst[5] = s_wTo + 2*1024*1024; tp.ld[5] = 2048;
    tp.src[6] = a_ow;          tp.dst[6] = s_wTaow;             tp.ld[6] = 1024;
    tp.src[7] = o_ow;          tp.dst[7] = s_wToow;             tp.ld[7] = 1024;
    tp.src[8] = ff2_w;         tp.dst[8] = s_wTff2;             tp.ld[8] = 1024;
    transpose_h_kernel<<<dim3(32, 32, 9), dim3(32, 8)>>>(tp);

    pos_kernel<<<(SEQ * D_MODEL) / 256, 256>>>(s_pos);
    embed_kernel<<<OUT_MAIN / 256, 256>>>(data, emb, s_pos, s_h0h);

    // self attention (layer); residual = h0h (fp16)
    run_attention(s_h0h, s_wTa, 0);
    gemm_h<false><<<dim3(8, 32), 128, GSMEM>>>(
        s_attnh, s_wTaow, s_h0h, s_proj, 1024, 1024, 1024, 1024);
    ln_kernel<<<MROWS, 256>>>(s_proj, a_g, a_b, nullptr, s_hidsh, out + OUT_MAIN);

    // OutputAttn (keys >= 1008 double-weighted); residual = hidsh (fp16)
    run_attention(s_hidsh, s_wTo, 1);
    gemm_h<false><<<dim3(8, 32), 128, GSMEM>>>(
        s_attnh, s_wToow, s_hidsh, s_proj, 1024, 1024, 1024, 1024);
    ln_ln_kernel<<<MROWS, 256>>>(s_proj, o_g, o_b, s_hidsh, ln1_g, ln1_b, s_outh);

    // output = LN(outh @ ff2 + outh, ln2); residual = outh (fp16)
    gemm_h<false><<<dim3(8, 32), 128, GSMEM>>>(
        s_outh, s_wTff2, s_outh, s_proj, 1024, 1024, 1024, 1024);
    ln_kernel<<<MROWS, 256>>>(s_proj, ln2_g, ln2_b, out, nullptr, nullptr);
}

// round 15
// speedup vs baseline: 1.0780x; 1.0343x over previous
#include <cuda_runtime.h>
#include <cuda_fp16.h>
#include <math.h>

// ---------------------------------------------------------------------------
// MemTransformerLMEncoder - fp16 mma.sync; persistent-CTA GEMM (tail-wave
// elimination), mbarrier-pipelined flash attention.
// Dead code: UpdateAttn branch + mem input unused. new_mem = hids[:,1008:1024].
// OutputAttn = 1024-key softmax with keys >=1008 double-weighted.
// Legacy-HMMA issue ceiling reached in-loop (~40% of tcgen05-normalized pipe);
// tcgen05 blocked by harness compute_103 virtual arch.
// ---------------------------------------------------------------------------

#define D_MODEL 1024
#define SEQ     1024
#define BATCH   4
#define NHEAD   16
#define DHEAD   64
#define MROWS   (BATCH*SEQ)            // 4096
#define OUT_MAIN (BATCH*SEQ*D_MODEL)   // 4194304
#define PERSIST_CTAS 296               // 148 SMs x 2 CTAs

// fp32 scratch
__device__ float g_proj[MROWS*D_MODEL];
__device__ float g_pos[SEQ*D_MODEL];
// fp16 scratch
__device__ __half g_h0h[MROWS*D_MODEL];
__device__ __half g_qkvh[MROWS*3*D_MODEL];
__device__ __half g_attnh[MROWS*D_MODEL];
__device__ __half g_hidsh[MROWS*D_MODEL];
__device__ __half g_outh[MROWS*D_MODEL];
// fp16 transposed weights
__device__ __half g_wTa[3*D_MODEL*D_MODEL];
__device__ __half g_wTo[3*D_MODEL*D_MODEL];
__device__ __half g_wTaow[D_MODEL*D_MODEL];
__device__ __half g_wToow[D_MODEL*D_MODEL];
__device__ __half g_wTff2[D_MODEL*D_MODEL];

// ---------------------------------------------------------------------------
__device__ __forceinline__ void mma16(float* c, const unsigned* a, unsigned b0, unsigned b1) {
    asm volatile(
        "mma.sync.aligned.m16n8k16.row.col.f32.f16.f16.f32 "
        "{%0,%1,%2,%3}, {%4,%5,%6,%7}, {%8,%9}, {%0,%1,%2,%3};"
        : "+f"(c[0]), "+f"(c[1]), "+f"(c[2]), "+f"(c[3])
        : "r"(a[0]), "r"(a[1]), "r"(a[2]), "r"(a[3]), "r"(b0), "r"(b1));
}
__device__ __forceinline__ void ldsm4(unsigned* r, unsigned addr) {
    asm volatile("ldmatrix.sync.aligned.m8n8.x4.shared.b16 {%0,%1,%2,%3}, [%4];"
        : "=r"(r[0]), "=r"(r[1]), "=r"(r[2]), "=r"(r[3]) : "r"(addr));
}
__device__ __forceinline__ void ldsm4t(unsigned* r, unsigned addr) {
    asm volatile("ldmatrix.sync.aligned.m8n8.x4.trans.shared.b16 {%0,%1,%2,%3}, [%4];"
        : "=r"(r[0]), "=r"(r[1]), "=r"(r[2]), "=r"(r[3]) : "r"(addr));
}
__device__ __forceinline__ void cp16(unsigned dst, const void* src) {
    asm volatile("cp.async.cg.shared.global [%0], [%1], 16;" :: "r"(dst), "l"(src));
}
__device__ __forceinline__ int off16(int lane, int STR) {
    return ((lane & 7) + ((lane >> 3) & 1) * 8) * STR + ((lane >> 4) & 1) * 8;
}
__device__ __forceinline__ int off16v(int lane, int STR) {
    return ((lane & 7) + ((lane >> 4) & 1) * 8) * STR + ((lane >> 3) & 1) * 8;
}
__device__ __forceinline__ unsigned packh2(float a, float b) {
    __half2 h = __floats2half2_rn(a, b);
    return *(unsigned*)&h;
}

#define MBAR_INIT(addr, cnt) \
    asm volatile("mbarrier.init.shared.b64 [%0], %1;" :: "r"(addr), "r"((unsigned)(cnt)) : "memory")
#define MBAR_ARRIVE(addr) \
    asm volatile("mbarrier.arrive.shared.b64 _, [%0];" :: "r"(addr) : "memory")
#define CP_ASYNC_MBAR_ARRIVE(addr) \
    asm volatile("cp.async.mbarrier.arrive.noinc.shared::cta.b64 [%0];" :: "r"(addr) : "memory")
#define MBAR_WAIT(mbar_addr, phase_parity) do { \
    unsigned _mb = (mbar_addr); \
    unsigned _ph = (phase_parity); \
    unsigned _done; \
    asm volatile( \
        "{\n\t.reg .pred p;\n\t" \
        "mbarrier.try_wait.parity.acquire.cta.shared::cta.b64 p, [%1], %2;\n\t" \
        "selp.b32 %0, 1, 0, p;\n\t}" \
        : "=r"(_done) : "r"(_mb), "r"(_ph) : "memory"); \
    if (!_done) { \
        asm volatile( \
            "{\n\t.reg .pred P1;\n\t" \
            "WL_%=:\n\t" \
            "mbarrier.try_wait.parity.acquire.cta.shared::cta.b64 P1, [%0], %1, 0x989680;\n\t" \
            "@P1 bra.uni WD_%=;\n\t" \
            "bra.uni WL_%=;\n\t" \
            "WD_%=:\n\t}" \
            :: "r"(_mb), "r"(_ph) : "memory"); \
    } \
} while (0)

// ---------------------------------------------------------------------------
// Positional table (depends only on s,d).
// ---------------------------------------------------------------------------
__global__ void pos_kernel(float* __restrict__ pos) {
    int idx = blockIdx.x * 256 + threadIdx.x;
    int d = idx & (D_MODEL - 1);
    int s = idx >> 10;
    float freq  = powf(10000.0f, -(float)(d & ~1) * (1.0f / 1024.0f));
    float angle = (float)s * freq;
    pos[idx] = (d & 1) ? cosf(angle) : sinf(angle);
}

__global__ void embed_kernel(const int* __restrict__ data,
                             const float* __restrict__ emb,
                             const float* __restrict__ pos,
                             __half* __restrict__ outh) {
    int idx = blockIdx.x * 256 + threadIdx.x;
    int d  = idx & (D_MODEL - 1);
    int bs = idx >> 10;
    int s  = bs & (SEQ - 1);
    int tok = data[bs];
    float v = emb[(size_t)tok * D_MODEL + d] * 32.0f + pos[(s << 10) + d];
    outh[idx] = __float2half(v);
}

// ---------------------------------------------------------------------------
// Fused transpose+fp16 convert: 9 units of 1024x1024
// ---------------------------------------------------------------------------
struct TpArgs {
    const float* src[9];
    __half* dst[9];
    int ld[9];
};
__global__ void transpose_h_kernel(TpArgs a) {
    __shared__ float tile[32][33];
    int u = blockIdx.z;
    const float* src = a.src[u];
    __half* dst = a.dst[u];
    int ld = a.ld[u];
    int kb = blockIdx.y * 32, nb = blockIdx.x * 32;
    int tx = threadIdx.x, ty = threadIdx.y;
    #pragma unroll
    for (int i = 0; i < 32; i += 8)
        tile[ty + i][tx] = src[(size_t)(kb + ty + i) * ld + nb + tx];
    __syncthreads();
    #pragma unroll
    for (int i = 0; i < 32; i += 8)
        dst[(size_t)(nb + ty + i) * 1024 + kb + tx] = __float2half(tile[tx][ty + i]);
}

// ---------------------------------------------------------------------------
// fp16 GEMM, persistent CTAs: fixed grid, each CTA loops over the
// (ntx x nty) tile space with stride gridDim.x. Per tile: 4 warps, 64x64
// warp tiles, CTA tile 128x128, BK=64, 2-stage cp.async, ldmatrix.
// C = A[M,K] @ B[N,K]^T (+fp16 resid). Inter-tile smem reuse is safe: every
// tile's K-loop ends with __syncthreads and the epilogue touches no smem.
// ---------------------------------------------------------------------------
#define GSTR 72
#define GAB  (128*GSTR*2)               // 18432 bytes per buffer
#define GSMEM (2*2*GAB)                 // 73728

template<bool OUTH>
__global__ __launch_bounds__(128, 2)
void gemm_h(const __half* __restrict__ A, const __half* __restrict__ B,
            const __half* __restrict__ resid, void* __restrict__ Cg,
            int K, int lda, int ldb, int ldc, int ntx, int nty) {
    extern __shared__ __align__(16) char smraw[];
    const int tid = threadIdx.x, lane = tid & 31, warp = tid >> 5;
    const int wm = (warp & 1) * 64, wn = (warp >> 1) * 64;
    const unsigned smBase = (unsigned)__cvta_generic_to_shared(smraw);
    const int offL = off16(lane, GSTR);
    const int T = K / 64;
    const int ntiles = ntx * nty;

    for (int tile = blockIdx.x; tile < ntiles; tile += gridDim.x) {
        const int row0 = (tile / ntx) * 128, col0 = (tile % ntx) * 128;

        float acc[4][8][4];
        #pragma unroll
        for (int mi = 0; mi < 4; mi++)
            #pragma unroll
            for (int ni = 0; ni < 8; ni++)
                #pragma unroll
                for (int c = 0; c < 4; c++) acc[mi][ni][c] = 0.0f;

        auto loadTile = [&](int t) {
            int buf = t & 1;
            unsigned aB = smBase + (unsigned)(buf * 2 * GAB);
            unsigned bB = aB + GAB;
            const __half* Asrc = A + (size_t)row0 * lda + t * 64;
            const __half* Bsrc = B + (size_t)col0 * ldb + t * 64;
            #pragma unroll
            for (int s = 0; s < 8; s++) {
                int c = tid + 128 * s;
                int m = c >> 3, kc = (c & 7) * 8;
                cp16(aB + (unsigned)(m * GSTR + kc) * 2u, Asrc + (size_t)m * lda + kc);
            }
            #pragma unroll
            for (int s = 0; s < 8; s++) {
                int c = tid + 128 * s;
                int n = c >> 3, kc = (c & 7) * 8;
                cp16(bB + (unsigned)(n * GSTR + kc) * 2u, Bsrc + (size_t)n * ldb + kc);
            }
        };

        loadTile(0);
        asm volatile("cp.async.commit_group;" ::: "memory");

        for (int t = 0; t < T; t++) {
            if (t + 1 < T) {
                loadTile(t + 1);
                asm volatile("cp.async.commit_group;" ::: "memory");
                asm volatile("cp.async.wait_group 1;" ::: "memory");
            } else {
                asm volatile("cp.async.wait_group 0;" ::: "memory");
            }
            __syncthreads();

            int buf = t & 1;
            unsigned aB = smBase + (unsigned)(buf * 2 * GAB);
            unsigned bB = aB + GAB;
            #pragma unroll
            for (int kk = 0; kk < 64; kk += 16) {
                unsigned af[4][4];
                #pragma unroll
                for (int mi = 0; mi < 4; mi++)
                    ldsm4(af[mi], aB + (unsigned)((wm + mi * 16) * GSTR + kk + offL) * 2u);
                #pragma unroll
                for (int g = 0; g < 4; g++) {
                    unsigned bf[4];
                    ldsm4(bf, bB + (unsigned)((wn + g * 16) * GSTR + kk + offL) * 2u);
                    #pragma unroll
                    for (int mi = 0; mi < 4; mi++) {
                        mma16(acc[mi][2 * g],     af[mi], bf[0], bf[2]);
                        mma16(acc[mi][2 * g + 1], af[mi], bf[1], bf[3]);
                    }
                }
            }
            __syncthreads();
        }

        {
            int q = lane >> 2, r2 = (lane & 3) * 2;
            #pragma unroll
            for (int mi = 0; mi < 4; mi++) {
                int row = row0 + wm + mi * 16 + q;
                #pragma unroll
                for (int ni = 0; ni < 8; ni++) {
                    int col = col0 + wn + ni * 8 + r2;
                    float v0 = acc[mi][ni][0], v1 = acc[mi][ni][1];
                    float v2 = acc[mi][ni][2], v3 = acc[mi][ni][3];
                    if (resid) {
                        __half2 r0 = ((const __half2*)resid)[((size_t)row * ldc + col) >> 1];
                        __half2 r1 = ((const __half2*)resid)[((size_t)(row + 8) * ldc + col) >> 1];
                        v0 += __low2float(r0); v1 += __high2float(r0);
                        v2 += __low2float(r1); v3 += __high2float(r1);
                    }
                    if (OUTH) {
                        __half2* C = (__half2*)Cg;
                        C[((size_t)row * ldc + col) >> 1]       = __floats2half2_rn(v0, v1);
                        C[((size_t)(row + 8) * ldc + col) >> 1] = __floats2half2_rn(v2, v3);
                    } else {
                        float* C = (float*)Cg;
                        *(float2*)&C[(size_t)row * ldc + col]       = make_float2(v0, v1);
                        *(float2*)&C[(size_t)(row + 8) * ldc + col] = make_float2(v2, v3);
                    }
                }
            }
        }
    }
}

// ---------------------------------------------------------------------------
// Flash attention, register-resident P, mbarrier-pipelined KV (round-14
// proven): 4-deep ring, prefetch distance 2, no block barriers in mainloop.
// ---------------------------------------------------------------------------
#define FSTR 72
#define FQ_HALVES (128*FSTR)            // 9216
#define FKVB 4608
#define KBUF(s) (FQ_HALVES + (s)*FKVB)
#define VBUF(s) (FQ_HALVES + 4*FKVB + (s)*FKVB)
#define FMB_OFF 92160
#define FA_SMEM (FMB_OFF + 64)

__global__ __launch_bounds__(256, 2)
void flash_h(const __half* __restrict__ qkv, __half* __restrict__ O, int extraFlag) {
    extern __shared__ __align__(16) char smraw[];
    const int tid = threadIdx.x, lane = tid & 31, warp = tid >> 5;
    const int wm = warp * 16;
    const int qb = blockIdx.x, bh = blockIdx.y;
    const int b = bh >> 4, h = bh & 15;
    const int qrow0 = qb * 128;

    const unsigned smBase = (unsigned)__cvta_generic_to_shared(smraw);
    const unsigned mbF = smBase + FMB_OFF;
    const unsigned mbE = smBase + FMB_OFF + 32;
    const int offL = off16(lane, FSTR);
    const int offV = off16v(lane, FSTR);

    if (tid == 0) {
        #pragma unroll
        for (int s = 0; s < 4; s++) {
            MBAR_INIT(mbF + 8u * s, 256);
            MBAR_INIT(mbE + 8u * s, 8);
        }
    }
    __syncthreads();

    const __half* base = qkv + (size_t)(b * SEQ) * 3072 + h * 64;

    auto loadKV = [&](int t, int s) {
        unsigned kB = smBase + (unsigned)KBUF(s) * 2u;
        unsigned vB = smBase + (unsigned)VBUF(s) * 2u;
        const __half* Ksrc = base + (size_t)(t * 64) * 3072 + 1024;
        const __half* Vsrc = base + (size_t)(t * 64) * 3072 + 2048;
        #pragma unroll
        for (int si = 0; si < 2; si++) {
            int c = tid + 256 * si;
            int n = c >> 3, kc = (c & 7) * 8;
            cp16(kB + (unsigned)(n * FSTR + kc) * 2u, Ksrc + (size_t)n * 3072 + kc);
            cp16(vB + (unsigned)(n * FSTR + kc) * 2u, Vsrc + (size_t)n * 3072 + kc);
        }
    };

    {
        const __half* Qsrc = base + (size_t)qrow0 * 3072;
        #pragma unroll
        for (int s = 0; s < 4; s++) {
            int c = tid + 256 * s;
            int m = c >> 3, kc = (c & 7) * 8;
            cp16(smBase + (unsigned)(m * FSTR + kc) * 2u, Qsrc + (size_t)m * 3072 + kc);
        }
    }
    loadKV(0, 0);
    CP_ASYNC_MBAR_ARRIVE(mbF + 0u);
    loadKV(1, 1);
    CP_ASYNC_MBAR_ARRIVE(mbF + 8u);
    asm volatile("cp.async.commit_group;" ::: "memory");
    asm volatile("cp.async.wait_group 0;" ::: "memory");
    __syncthreads();

    float m0 = -INFINITY, m1 = -INFINITY, l0 = 0.0f, l1 = 0.0f;
    float oacc[8][4];
    #pragma unroll
    for (int ni = 0; ni < 8; ni++)
        #pragma unroll
        for (int c = 0; c < 4; c++) oacc[ni][c] = 0.0f;

    for (int t = 0; t < 16; t++) {
        int pf = t + 2;
        if (pf < 16) {
            int s2 = pf & 3;
            MBAR_WAIT(mbE + 8u * s2, ((pf >> 2) + 1) & 1);
            loadKV(pf, s2);
            CP_ASYNC_MBAR_ARRIVE(mbF + 8u * s2);
        }
        int s = t & 3;
        MBAR_WAIT(mbF + 8u * s, (t >> 2) & 1);
        unsigned kB = smBase + (unsigned)KBUF(s) * 2u;
        unsigned vB = smBase + (unsigned)VBUF(s) * 2u;

        float sc[8][4];
        #pragma unroll
        for (int ni = 0; ni < 8; ni++)
            #pragma unroll
            for (int c = 0; c < 4; c++) sc[ni][c] = 0.0f;
        #pragma unroll
        for (int kki = 0; kki < 4; kki++) {
            int kk = kki * 16;
            unsigned af[4];
            ldsm4(af, smBase + (unsigned)(wm * FSTR + kk + offL) * 2u);
            #pragma unroll
            for (int g = 0; g < 4; g++) {
                unsigned bf[4];
                ldsm4(bf, kB + (unsigned)((g * 16) * FSTR + kk + offL) * 2u);
                mma16(sc[2 * g],     af, bf[0], bf[2]);
                mma16(sc[2 * g + 1], af, bf[1], bf[3]);
            }
        }

        float rm0 = -INFINITY, rm1 = -INFINITY;
        #pragma unroll
        for (int ni = 0; ni < 8; ni++) {
            sc[ni][0] *= 0.125f; sc[ni][1] *= 0.125f;
            sc[ni][2] *= 0.125f; sc[ni][3] *= 0.125f;
            rm0 = fmaxf(rm0, fmaxf(sc[ni][0], sc[ni][1]));
            rm1 = fmaxf(rm1, fmaxf(sc[ni][2], sc[ni][3]));
        }
        rm0 = fmaxf(rm0, __shfl_xor_sync(0xffffffff, rm0, 1));
        rm0 = fmaxf(rm0, __shfl_xor_sync(0xffffffff, rm0, 2));
        rm1 = fmaxf(rm1, __shfl_xor_sync(0xffffffff, rm1, 1));
        rm1 = fmaxf(rm1, __shfl_xor_sync(0xffffffff, rm1, 2));
        float nm0 = fmaxf(m0, rm0), nm1 = fmaxf(m1, rm1);
        float c0 = __expf(m0 - nm0), c1 = __expf(m1 - nm1);
        m0 = nm0; m1 = nm1;
        float s0 = 0.0f, s1 = 0.0f;
        bool dbl = extraFlag && (t == 15);
        #pragma unroll
        for (int ni = 0; ni < 8; ni++) {
            float p00 = __expf(sc[ni][0] - nm0);
            float p01 = __expf(sc[ni][1] - nm0);
            float p10 = __expf(sc[ni][2] - nm1);
            float p11 = __expf(sc[ni][3] - nm1);
            if (dbl && ni >= 6) { p00 *= 2.f; p01 *= 2.f; p10 *= 2.f; p11 *= 2.f; }
            s0 += p00 + p01; s1 += p10 + p11;
            sc[ni][0] = p00; sc[ni][1] = p01; sc[ni][2] = p10; sc[ni][3] = p11;
        }
        s0 += __shfl_xor_sync(0xffffffff, s0, 1);
        s0 += __shfl_xor_sync(0xffffffff, s0, 2);
        s1 += __shfl_xor_sync(0xffffffff, s1, 1);
        s1 += __shfl_xor_sync(0xffffffff, s1, 2);
        l0 = l0 * c0 + s0;
        l1 = l1 * c1 + s1;

        #pragma unroll
        for (int ni = 0; ni < 8; ni++) {
            oacc[ni][0] *= c0; oacc[ni][1] *= c0;
            oacc[ni][2] *= c1; oacc[ni][3] *= c1;
        }
        #pragma unroll
        for (int kki = 0; kki < 4; kki++) {
            int ni0 = 2 * kki;
            unsigned af2[4];
            af2[0] = packh2(sc[ni0][0],     sc[ni0][1]);
            af2[1] = packh2(sc[ni0][2],     sc[ni0][3]);
            af2[2] = packh2(sc[ni0 + 1][0], sc[ni0 + 1][1]);
            af2[3] = packh2(sc[ni0 + 1][2], sc[ni0 + 1][3]);
            #pragma unroll
            for (int g = 0; g < 4; g++) {
                unsigned bf[4];
                ldsm4t(bf, vB + (unsigned)((kki * 16) * FSTR + g * 16 + offV) * 2u);
                mma16(oacc[2 * g],     af2, bf[0], bf[2]);
                mma16(oacc[2 * g + 1], af2, bf[1], bf[3]);
            }
        }
        if (lane == 0) MBAR_ARRIVE(mbE + 8u * s);
    }

    {
        int q = lane >> 2, r2c = (lane & 3) * 2;
        float i0 = 1.0f / l0, i1 = 1.0f / l1;
        int row0 = qrow0 + wm + q;
        #pragma unroll
        for (int ni = 0; ni < 8; ni++) {
            int col = h * 64 + ni * 8 + r2c;
            size_t g0 = (size_t)(b * SEQ + row0) * D_MODEL + col;
            size_t g1 = (size_t)(b * SEQ + row0 + 8) * D_MODEL + col;
            ((__half2*)O)[g0 >> 1] = __floats2half2_rn(oacc[ni][0] * i0, oacc[ni][1] * i0);
            ((__half2*)O)[g1 >> 1] = __floats2half2_rn(oacc[ni][2] * i1, oacc[ni][3] * i1);
        }
    }
}

// ---------------------------------------------------------------------------
// Reductions / LN
// ---------------------------------------------------------------------------
__device__ __forceinline__ float block_reduce_sum(float val, float* sdata) {
    int t = threadIdx.x;
    #pragma unroll
    for (int off = 16; off > 0; off >>= 1)
        val += __shfl_down_sync(0xffffffff, val, off);
    if ((t & 31) == 0) sdata[t >> 5] = val;
    __syncthreads();
    if (t < 32) {
        float v = (t < 8) ? sdata[t] : 0.0f;
        #pragma unroll
        for (int off = 4; off > 0; off >>= 1)
            v += __shfl_down_sync(0xffffffff, v, off);
        if (t == 0) sdata[0] = v;
    }
    __syncthreads();
    float r = sdata[0];
    __syncthreads();
    return r;
}

__global__ __launch_bounds__(256)
void ln_kernel(const float* __restrict__ x, const float* __restrict__ g,
               const float* __restrict__ bb, float* __restrict__ outf,
               __half* __restrict__ outh, float* __restrict__ memout) {
    __shared__ float sdata[32];
    int row = blockIdx.x;
    int t = threadIdx.x;
    const float* xr = x + (size_t)row * D_MODEL;
    float v[4];
    #pragma unroll
    for (int i = 0; i < 4; i++) v[i] = xr[t + 256 * i];
    float s = v[0] + v[1] + v[2] + v[3];
    float mu = block_reduce_sum(s, sdata) * (1.0f / 1024.0f);
    float sq = 0.f;
    #pragma unroll
    for (int i = 0; i < 4; i++) { float d0 = v[i] - mu; sq += d0 * d0; }
    float var = block_reduce_sum(sq, sdata) * (1.0f / 1024.0f);
    float inv = 1.0f / sqrtf(var + 1e-5f);
    int srow = row & (SEQ - 1), bidx = row >> 10;
    bool isMem = memout && (srow >= 1008);
    float* mrow = isMem ? memout + ((size_t)(bidx * 16 + srow - 1008)) * D_MODEL : nullptr;
    #pragma unroll
    for (int i = 0; i < 4; i++) {
        int c = t + 256 * i;
        float o = (v[i] - mu) * inv * g[c] + bb[c];
        if (outf) outf[(size_t)row * D_MODEL + c] = o;
        if (outh) outh[(size_t)row * D_MODEL + c] = __float2half(o);
        if (isMem) mrow[c] = o;
    }
}

__global__ __launch_bounds__(256)
void ln_ln_kernel(const float* __restrict__ proj,
                  const float* __restrict__ g1, const float* __restrict__ b1,
                  const __half* __restrict__ hidsh,
                  const float* __restrict__ g2, const float* __restrict__ b2,
                  __half* __restrict__ outh) {
    __shared__ float sdata[32];
    int row = blockIdx.x;
    int t = threadIdx.x;
    const float* xr = proj + (size_t)row * D_MODEL;
    const __half* hr = hidsh + (size_t)row * D_MODEL;
    float v[4], hv[4];
    #pragma unroll
    for (int i = 0; i < 4; i++) { v[i] = xr[t + 256 * i]; hv[i] = __half2float(hr[t + 256 * i]); }
    float s = v[0] + v[1] + v[2] + v[3];
    float mu = block_reduce_sum(s, sdata) * (1.0f / 1024.0f);
    float sq = 0.f;
    #pragma unroll
    for (int i = 0; i < 4; i++) { float d0 = v[i] - mu; sq += d0 * d0; }
    float var = block_reduce_sum(sq, sdata) * (1.0f / 1024.0f);
    float inv = 1.0f / sqrtf(var + 1e-5f);
    float y[4];
    #pragma unroll
    for (int i = 0; i < 4; i++) {
        int c = t + 256 * i;
        y[i] = hv[i] + (v[i] - mu) * inv * g1[c] + b1[c];
    }
    float s2 = y[0] + y[1] + y[2] + y[3];
    float mu2 = block_reduce_sum(s2, sdata) * (1.0f / 1024.0f);
    float sq2 = 0.f;
    #pragma unroll
    for (int i = 0; i < 4; i++) { float d0 = y[i] - mu2; sq2 += d0 * d0; }
    float var2 = block_reduce_sum(sq2, sdata) * (1.0f / 1024.0f);
    float inv2 = 1.0f / sqrtf(var2 + 1e-5f);
    #pragma unroll
    for (int i = 0; i < 4; i++) {
        int c = t + 256 * i;
        float o = (y[i] - mu2) * inv2 * g2[c] + b2[c];
        outh[(size_t)row * D_MODEL + c] = __float2half(o);
    }
}

// ---------------------------------------------------------------------------
static float *s_proj = 0, *s_pos = 0;
static __half *s_h0h = 0, *s_qkvh = 0, *s_attnh = 0, *s_hidsh = 0, *s_outh = 0;
static __half *s_wTa = 0, *s_wTo = 0, *s_wTaow = 0, *s_wToow = 0, *s_wTff2 = 0;

static void resolve_scratch() {
    if (s_proj) return;
    cudaGetSymbolAddress((void**)&s_proj,  g_proj);
    cudaGetSymbolAddress((void**)&s_pos,   g_pos);
    cudaGetSymbolAddress((void**)&s_h0h,   g_h0h);
    cudaGetSymbolAddress((void**)&s_qkvh,  g_qkvh);
    cudaGetSymbolAddress((void**)&s_attnh, g_attnh);
    cudaGetSymbolAddress((void**)&s_hidsh, g_hidsh);
    cudaGetSymbolAddress((void**)&s_outh,  g_outh);
    cudaGetSymbolAddress((void**)&s_wTa,   g_wTa);
    cudaGetSymbolAddress((void**)&s_wTo,   g_wTo);
    cudaGetSymbolAddress((void**)&s_wTaow, g_wTaow);
    cudaGetSymbolAddress((void**)&s_wToow, g_wToow);
    cudaGetSymbolAddress((void**)&s_wTff2, g_wTff2);
    cudaFuncSetAttribute(gemm_h<false>, cudaFuncAttributeMaxDynamicSharedMemorySize, GSMEM);
    cudaFuncSetAttribute(gemm_h<true>,  cudaFuncAttributeMaxDynamicSharedMemorySize, GSMEM);
    cudaFuncSetAttribute(flash_h, cudaFuncAttributeMaxDynamicSharedMemorySize, FA_SMEM);
}

static void run_attention(const __half* xh, const __half* wT, int extraFlag) {
    // persistent qkv projection: 24x32 = 768 tiles over 296 CTAs
    gemm_h<true><<<PERSIST_CTAS, 128, GSMEM>>>(
        xh, wT, nullptr, s_qkvh, 1024, 1024, 1024, 3072, 24, 32);
    flash_h<<<dim3(8, BATCH * NHEAD), 256, FA_SMEM>>>(s_qkvh, s_attnh, extraFlag);
}

extern "C" void kernel_launch(void* const* d_in, const int* in_sizes, int n_in,
                              void* d_out, int out_size) {
    const int*   data  = (const int*)d_in[0];
    const float* emb   = (const float*)d_in[2];
    const float* a_qw  = (const float*)d_in[3];
    const float* a_kvw = (const float*)d_in[4];
    const float* a_ow  = (const float*)d_in[5];
    const float* a_g   = (const float*)d_in[6];
    const float* a_b   = (const float*)d_in[7];
    const float* o_qw  = (const float*)d_in[16];
    const float* o_kvw = (const float*)d_in[17];
    const float* o_ow  = (const float*)d_in[18];
    const float* o_g   = (const float*)d_in[19];
    const float* o_b   = (const float*)d_in[20];
    const float* ff2_w = (const float*)d_in[21];
    const float* ln1_g = (const float*)d_in[22];
    const float* ln1_b = (const float*)d_in[23];
    const float* ln2_g = (const float*)d_in[24];
    const float* ln2_b = (const float*)d_in[25];
    float* out = (float*)d_out;

    resolve_scratch();

    TpArgs tp;
    tp.src[0] = a_qw;          tp.dst[0] = s_wTa;               tp.ld[0] = 1024;
    tp.src[1] = a_kvw;         tp.dst[1] = s_wTa + 1024*1024;   tp.ld[1] = 2048;
    tp.src[2] = a_kvw + 1024;  tp.dst[2] = s_wTa + 2*1024*1024; tp.ld[2] = 2048;
    tp.src[3] = o_qw;          tp.dst[3] = s_wTo;               tp.ld[3] = 1024;
    tp.src[4] = o_kvw;         tp.dst[4] = s_wTo + 1024*1024;   tp.ld[4] = 2048;
    tp.src[5] = o_kvw + 1024;  tp.dst[5] = s_wTo + 2*1024*1024; tp.ld[5] = 2048;
    tp.src[6] = a_ow;          tp.dst[6] = s_wTaow;             tp.ld[6] = 1024;
    tp.src[7] = o_ow;          tp.dst[7] = s_wToow;             tp.ld[7] = 1024;
    tp.src[8] = ff2_w;         tp.dst[8] = s_wTff2;             tp.ld[8] = 1024;
    transpose_h_kernel<<<dim3(32, 32, 9), dim3(32, 8)>>>(tp);

    pos_kernel<<<(SEQ * D_MODEL) / 256, 256>>>(s_pos);
    embed_kernel<<<OUT_MAIN / 256, 256>>>(data, emb, s_pos, s_h0h);

    // self attention (layer); residual = h0h (fp16)
    run_attention(s_h0h, s_wTa, 0);
    gemm_h<false><<<256, 128, GSMEM>>>(
        s_attnh, s_wTaow, s_h0h, s_proj, 1024, 1024, 1024, 1024, 8, 32);
    ln_kernel<<<MROWS, 256>>>(s_proj, a_g, a_b, nullptr, s_hidsh, out + OUT_MAIN);

    // OutputAttn (keys >= 1008 double-weighted); residual = hidsh (fp16)
    run_attention(s_hidsh, s_wTo, 1);
    gemm_h<false><<<256, 128, GSMEM>>>(
        s_attnh, s_wToow, s_hidsh, s_proj, 1024, 1024, 1024, 1024, 8, 32);
    ln_ln_kernel<<<MROWS, 256>>>(s_proj, o_g, o_b, s_hidsh, ln1_g, ln1_b, s_outh);

    // output = LN(outh @ ff2 + outh, ln2); residual = outh (fp16)
    gemm_h<false><<<256, 128, GSMEM>>>(
        s_outh, s_wTff2, s_outh, s_proj, 1024, 1024, 1024, 1024, 8, 32);
    ln_kernel<<<MROWS, 256>>>(s_proj, ln2_g, ln2_b, out, nullptr, nullptr);
}

// round 17
// speedup vs baseline: 1.0801x; 1.0020x over previous
#include <cuda_runtime.h>
#include <cuda_fp16.h>
#include <math.h>

// ---------------------------------------------------------------------------
// MemTransformerLMEncoder - fp16 mma.sync; persistent-CTA GEMM; mbarrier-
// pipelined flash attention; fully fp16 activation stream (fp32 only inside
// LN statistics and the final output / new_mem).
// Dead code: UpdateAttn branch + mem input unused. new_mem = hids[:,1008:1024].
// OutputAttn = 1024-key softmax with keys >=1008 double-weighted.
// GEMMs at ~94% of measured legacy-HMMA ceiling; tcgen05 blocked by the
// harness's compute_103 virtual arch.
// ---------------------------------------------------------------------------

#define D_MODEL 1024
#define SEQ     1024
#define BATCH   4
#define NHEAD   16
#define DHEAD   64
#define MROWS   (BATCH*SEQ)            // 4096
#define OUT_MAIN (BATCH*SEQ*D_MODEL)   // 4194304
#define PERSIST_CTAS 296               // 148 SMs x 2 CTAs

// fp32 scratch
__device__ float g_pos[SEQ*D_MODEL];
// fp16 scratch
__device__ __half g_h0h[MROWS*D_MODEL];
__device__ __half g_qkvh[MROWS*3*D_MODEL];
__device__ __half g_attnh[MROWS*D_MODEL];
__device__ __half g_projh[MROWS*D_MODEL];
__device__ __half g_hidsh[MROWS*D_MODEL];
__device__ __half g_outh[MROWS*D_MODEL];
// fp16 transposed weights
__device__ __half g_wTa[3*D_MODEL*D_MODEL];
__device__ __half g_wTo[3*D_MODEL*D_MODEL];
__device__ __half g_wTaow[D_MODEL*D_MODEL];
__device__ __half g_wToow[D_MODEL*D_MODEL];
__device__ __half g_wTff2[D_MODEL*D_MODEL];

// ---------------------------------------------------------------------------
__device__ __forceinline__ void mma16(float* c, const unsigned* a, unsigned b0, unsigned b1) {
    asm volatile(
        "mma.sync.aligned.m16n8k16.row.col.f32.f16.f16.f32 "
        "{%0,%1,%2,%3}, {%4,%5,%6,%7}, {%8,%9}, {%0,%1,%2,%3};"
        : "+f"(c[0]), "+f"(c[1]), "+f"(c[2]), "+f"(c[3])
        : "r"(a[0]), "r"(a[1]), "r"(a[2]), "r"(a[3]), "r"(b0), "r"(b1));
}
__device__ __forceinline__ void ldsm4(unsigned* r, unsigned addr) {
    asm volatile("ldmatrix.sync.aligned.m8n8.x4.shared.b16 {%0,%1,%2,%3}, [%4];"
        : "=r"(r[0]), "=r"(r[1]), "=r"(r[2]), "=r"(r[3]) : "r"(addr));
}
__device__ __forceinline__ void ldsm4t(unsigned* r, unsigned addr) {
    asm volatile("ldmatrix.sync.aligned.m8n8.x4.trans.shared.b16 {%0,%1,%2,%3}, [%4];"
        : "=r"(r[0]), "=r"(r[1]), "=r"(r[2]), "=r"(r[3]) : "r"(addr));
}
__device__ __forceinline__ void cp16(unsigned dst, const void* src) {
    asm volatile("cp.async.cg.shared.global [%0], [%1], 16;" :: "r"(dst), "l"(src));
}
__device__ __forceinline__ int off16(int lane, int STR) {
    return ((lane & 7) + ((lane >> 3) & 1) * 8) * STR + ((lane >> 4) & 1) * 8;
}
__device__ __forceinline__ int off16v(int lane, int STR) {
    return ((lane & 7) + ((lane >> 4) & 1) * 8) * STR + ((lane >> 3) & 1) * 8;
}
__device__ __forceinline__ unsigned packh2(float a, float b) {
    __half2 h = __floats2half2_rn(a, b);
    return *(unsigned*)&h;
}

#define MBAR_INIT(addr, cnt) \
    asm volatile("mbarrier.init.shared.b64 [%0], %1;" :: "r"(addr), "r"((unsigned)(cnt)) : "memory")
#define MBAR_ARRIVE(addr) \
    asm volatile("mbarrier.arrive.shared.b64 _, [%0];" :: "r"(addr) : "memory")
#define CP_ASYNC_MBAR_ARRIVE(addr) \
    asm volatile("cp.async.mbarrier.arrive.noinc.shared::cta.b64 [%0];" :: "r"(addr) : "memory")
#define MBAR_WAIT(mbar_addr, phase_parity) do { \
    unsigned _mb = (mbar_addr); \
    unsigned _ph = (phase_parity); \
    unsigned _done; \
    asm volatile( \
        "{\n\t.reg .pred p;\n\t" \
        "mbarrier.try_wait.parity.acquire.cta.shared::cta.b64 p, [%1], %2;\n\t" \
        "selp.b32 %0, 1, 0, p;\n\t}" \
        : "=r"(_done) : "r"(_mb), "r"(_ph) : "memory"); \
    if (!_done) { \
        asm volatile( \
            "{\n\t.reg .pred P1;\n\t" \
            "WL_%=:\n\t" \
            "mbarrier.try_wait.parity.acquire.cta.shared::cta.b64 P1, [%0], %1, 0x989680;\n\t" \
            "@P1 bra.uni WD_%=;\n\t" \
            "bra.uni WL_%=;\n\t" \
            "WD_%=:\n\t}" \
            :: "r"(_mb), "r"(_ph) : "memory"); \
    } \
} while (0)

// ---------------------------------------------------------------------------
// Positional table (depends only on s,d).
// ---------------------------------------------------------------------------
__global__ void pos_kernel(float* __restrict__ pos) {
    int idx = blockIdx.x * 256 + threadIdx.x;
    int d = idx & (D_MODEL - 1);
    int s = idx >> 10;
    float freq  = powf(10000.0f, -(float)(d & ~1) * (1.0f / 1024.0f));
    float angle = (float)s * freq;
    pos[idx] = (d & 1) ? cosf(angle) : sinf(angle);
}

__global__ void embed_kernel(const int* __restrict__ data,
                             const float* __restrict__ emb,
                             const float* __restrict__ pos,
                             __half* __restrict__ outh) {
    int idx = blockIdx.x * 256 + threadIdx.x;
    int d  = idx & (D_MODEL - 1);
    int bs = idx >> 10;
    int s  = bs & (SEQ - 1);
    int tok = data[bs];
    float v = emb[(size_t)tok * D_MODEL + d] * 32.0f + pos[(s << 10) + d];
    outh[idx] = __float2half(v);
}

// ---------------------------------------------------------------------------
// Fused transpose+fp16 convert: 9 units of 1024x1024
// ---------------------------------------------------------------------------
struct TpArgs {
    const float* src[9];
    __half* dst[9];
    int ld[9];
};
__global__ void transpose_h_kernel(TpArgs a) {
    __shared__ float tile[32][33];
    int u = blockIdx.z;
    const float* src = a.src[u];
    __half* dst = a.dst[u];
    int ld = a.ld[u];
    int kb = blockIdx.y * 32, nb = blockIdx.x * 32;
    int tx = threadIdx.x, ty = threadIdx.y;
    #pragma unroll
    for (int i = 0; i < 32; i += 8)
        tile[ty + i][tx] = src[(size_t)(kb + ty + i) * ld + nb + tx];
    __syncthreads();
    #pragma unroll
    for (int i = 0; i < 32; i += 8)
        dst[(size_t)(nb + ty + i) * 1024 + kb + tx] = __float2half(tile[tx][ty + i]);
}

// ---------------------------------------------------------------------------
// fp16 GEMM, persistent CTAs: fixed grid, each CTA loops over the (ntx x nty)
// tile space with stride gridDim.x. 4 warps, 64x64 warp tiles, CTA 128x128,
// BK=64, 2-stage cp.async, ldmatrix. C(fp16) = A[M,K] @ B[N,K]^T (+fp16 resid).
// ---------------------------------------------------------------------------
#define GSTR 72
#define GAB  (128*GSTR*2)               // 18432 bytes per buffer
#define GSMEM (2*2*GAB)                 // 73728

__global__ __launch_bounds__(128, 2)
void gemm_h(const __half* __restrict__ A, const __half* __restrict__ B,
            const __half* __restrict__ resid, __half* __restrict__ Cg,
            int K, int lda, int ldb, int ldc, int ntx, int nty) {
    extern __shared__ __align__(16) char smraw[];
    const int tid = threadIdx.x, lane = tid & 31, warp = tid >> 5;
    const int wm = (warp & 1) * 64, wn = (warp >> 1) * 64;
    const unsigned smBase = (unsigned)__cvta_generic_to_shared(smraw);
    const int offL = off16(lane, GSTR);
    const int T = K / 64;
    const int ntiles = ntx * nty;

    for (int tile = blockIdx.x; tile < ntiles; tile += gridDim.x) {
        const int row0 = (tile / ntx) * 128, col0 = (tile % ntx) * 128;

        float acc[4][8][4];
        #pragma unroll
        for (int mi = 0; mi < 4; mi++)
            #pragma unroll
            for (int ni = 0; ni < 8; ni++)
                #pragma unroll
                for (int c = 0; c < 4; c++) acc[mi][ni][c] = 0.0f;

        auto loadTile = [&](int t) {
            int buf = t & 1;
            unsigned aB = smBase + (unsigned)(buf * 2 * GAB);
            unsigned bB = aB + GAB;
            const __half* Asrc = A + (size_t)row0 * lda + t * 64;
            const __half* Bsrc = B + (size_t)col0 * ldb + t * 64;
            #pragma unroll
            for (int s = 0; s < 8; s++) {
                int c = tid + 128 * s;
                int m = c >> 3, kc = (c & 7) * 8;
                cp16(aB + (unsigned)(m * GSTR + kc) * 2u, Asrc + (size_t)m * lda + kc);
            }
            #pragma unroll
            for (int s = 0; s < 8; s++) {
                int c = tid + 128 * s;
                int n = c >> 3, kc = (c & 7) * 8;
                cp16(bB + (unsigned)(n * GSTR + kc) * 2u, Bsrc + (size_t)n * ldb + kc);
            }
        };

        loadTile(0);
        asm volatile("cp.async.commit_group;" ::: "memory");

        for (int t = 0; t < T; t++) {
            if (t + 1 < T) {
                loadTile(t + 1);
                asm volatile("cp.async.commit_group;" ::: "memory");
                asm volatile("cp.async.wait_group 1;" ::: "memory");
            } else {
                asm volatile("cp.async.wait_group 0;" ::: "memory");
            }
            __syncthreads();

            int buf = t & 1;
            unsigned aB = smBase + (unsigned)(buf * 2 * GAB);
            unsigned bB = aB + GAB;
            #pragma unroll
            for (int kk = 0; kk < 64; kk += 16) {
                unsigned af[4][4];
                #pragma unroll
                for (int mi = 0; mi < 4; mi++)
                    ldsm4(af[mi], aB + (unsigned)((wm + mi * 16) * GSTR + kk + offL) * 2u);
                #pragma unroll
                for (int g = 0; g < 4; g++) {
                    unsigned bf[4];
                    ldsm4(bf, bB + (unsigned)((wn + g * 16) * GSTR + kk + offL) * 2u);
                    #pragma unroll
                    for (int mi = 0; mi < 4; mi++) {
                        mma16(acc[mi][2 * g],     af[mi], bf[0], bf[2]);
                        mma16(acc[mi][2 * g + 1], af[mi], bf[1], bf[3]);
                    }
                }
            }
            __syncthreads();
        }

        {
            int q = lane >> 2, r2 = (lane & 3) * 2;
            #pragma unroll
            for (int mi = 0; mi < 4; mi++) {
                int row = row0 + wm + mi * 16 + q;
                #pragma unroll
                for (int ni = 0; ni < 8; ni++) {
                    int col = col0 + wn + ni * 8 + r2;
                    float v0 = acc[mi][ni][0], v1 = acc[mi][ni][1];
                    float v2 = acc[mi][ni][2], v3 = acc[mi][ni][3];
                    if (resid) {
                        __half2 r0 = ((const __half2*)resid)[((size_t)row * ldc + col) >> 1];
                        __half2 r1 = ((const __half2*)resid)[((size_t)(row + 8) * ldc + col) >> 1];
                        v0 += __low2float(r0); v1 += __high2float(r0);
                        v2 += __low2float(r1); v3 += __high2float(r1);
                    }
                    __half2* C = (__half2*)Cg;
                    C[((size_t)row * ldc + col) >> 1]       = __floats2half2_rn(v0, v1);
                    C[((size_t)(row + 8) * ldc + col) >> 1] = __floats2half2_rn(v2, v3);
                }
            }
        }
    }
}

// ---------------------------------------------------------------------------
// Flash attention, register-resident P, mbarrier-pipelined KV (round-14
// proven): 4-deep ring, prefetch distance 2, no block barriers in mainloop.
// ---------------------------------------------------------------------------
#define FSTR 72
#define FQ_HALVES (128*FSTR)            // 9216
#define FKVB 4608
#define KBUF(s) (FQ_HALVES + (s)*FKVB)
#define VBUF(s) (FQ_HALVES + 4*FKVB + (s)*FKVB)
#define FMB_OFF 92160
#define FA_SMEM (FMB_OFF + 64)

__global__ __launch_bounds__(256, 2)
void flash_h(const __half* __restrict__ qkv, __half* __restrict__ O, int extraFlag) {
    extern __shared__ __align__(16) char smraw[];
    const int tid = threadIdx.x, lane = tid & 31, warp = tid >> 5;
    const int wm = warp * 16;
    const int qb = blockIdx.x, bh = blockIdx.y;
    const int b = bh >> 4, h = bh & 15;
    const int qrow0 = qb * 128;

    const unsigned smBase = (unsigned)__cvta_generic_to_shared(smraw);
    const unsigned mbF = smBase + FMB_OFF;
    const unsigned mbE = smBase + FMB_OFF + 32;
    const int offL = off16(lane, FSTR);
    const int offV = off16v(lane, FSTR);

    if (tid == 0) {
        #pragma unroll
        for (int s = 0; s < 4; s++) {
            MBAR_INIT(mbF + 8u * s, 256);
            MBAR_INIT(mbE + 8u * s, 8);
        }
    }
    __syncthreads();

    const __half* base = qkv + (size_t)(b * SEQ) * 3072 + h * 64;

    auto loadKV = [&](int t, int s) {
        unsigned kB = smBase + (unsigned)KBUF(s) * 2u;
        unsigned vB = smBase + (unsigned)VBUF(s) * 2u;
        const __half* Ksrc = base + (size_t)(t * 64) * 3072 + 1024;
        const __half* Vsrc = base + (size_t)(t * 64) * 3072 + 2048;
        #pragma unroll
        for (int si = 0; si < 2; si++) {
            int c = tid + 256 * si;
            int n = c >> 3, kc = (c & 7) * 8;
            cp16(kB + (unsigned)(n * FSTR + kc) * 2u, Ksrc + (size_t)n * 3072 + kc);
            cp16(vB + (unsigned)(n * FSTR + kc) * 2u, Vsrc + (size_t)n * 3072 + kc);
        }
    };

    {
        const __half* Qsrc = base + (size_t)qrow0 * 3072;
        #pragma unroll
        for (int s = 0; s < 4; s++) {
            int c = tid + 256 * s;
            int m = c >> 3, kc = (c & 7) * 8;
            cp16(smBase + (unsigned)(m * FSTR + kc) * 2u, Qsrc + (size_t)m * 3072 + kc);
        }
    }
    loadKV(0, 0);
    CP_ASYNC_MBAR_ARRIVE(mbF + 0u);
    loadKV(1, 1);
    CP_ASYNC_MBAR_ARRIVE(mbF + 8u);
    asm volatile("cp.async.commit_group;" ::: "memory");
    asm volatile("cp.async.wait_group 0;" ::: "memory");
    __syncthreads();

    float m0 = -INFINITY, m1 = -INFINITY, l0 = 0.0f, l1 = 0.0f;
    float oacc[8][4];
    #pragma unroll
    for (int ni = 0; ni < 8; ni++)
        #pragma unroll
        for (int c = 0; c < 4; c++) oacc[ni][c] = 0.0f;

    for (int t = 0; t < 16; t++) {
        int pf = t + 2;
        if (pf < 16) {
            int s2 = pf & 3;
            MBAR_WAIT(mbE + 8u * s2, ((pf >> 2) + 1) & 1);
            loadKV(pf, s2);
            CP_ASYNC_MBAR_ARRIVE(mbF + 8u * s2);
        }
        int s = t & 3;
        MBAR_WAIT(mbF + 8u * s, (t >> 2) & 1);
        unsigned kB = smBase + (unsigned)KBUF(s) * 2u;
        unsigned vB = smBase + (unsigned)VBUF(s) * 2u;

        float sc[8][4];
        #pragma unroll
        for (int ni = 0; ni < 8; ni++)
            #pragma unroll
            for (int c = 0; c < 4; c++) sc[ni][c] = 0.0f;
        #pragma unroll
        for (int kki = 0; kki < 4; kki++) {
            int kk = kki * 16;
            unsigned af[4];
            ldsm4(af, smBase + (unsigned)(wm * FSTR + kk + offL) * 2u);
            #pragma unroll
            for (int g = 0; g < 4; g++) {
                unsigned bf[4];
                ldsm4(bf, kB + (unsigned)((g * 16) * FSTR + kk + offL) * 2u);
                mma16(sc[2 * g],     af, bf[0], bf[2]);
                mma16(sc[2 * g + 1], af, bf[1], bf[3]);
            }
        }

        float rm0 = -INFINITY, rm1 = -INFINITY;
        #pragma unroll
        for (int ni = 0; ni < 8; ni++) {
            sc[ni][0] *= 0.125f; sc[ni][1] *= 0.125f;
            sc[ni][2] *= 0.125f; sc[ni][3] *= 0.125f;
            rm0 = fmaxf(rm0, fmaxf(sc[ni][0], sc[ni][1]));
            rm1 = fmaxf(rm1, fmaxf(sc[ni][2], sc[ni][3]));
        }
        rm0 = fmaxf(rm0, __shfl_xor_sync(0xffffffff, rm0, 1));
        rm0 = fmaxf(rm0, __shfl_xor_sync(0xffffffff, rm0, 2));
        rm1 = fmaxf(rm1, __shfl_xor_sync(0xffffffff, rm1, 1));
        rm1 = fmaxf(rm1, __shfl_xor_sync(0xffffffff, rm1, 2));
        float nm0 = fmaxf(m0, rm0), nm1 = fmaxf(m1, rm1);
        float c0 = __expf(m0 - nm0), c1 = __expf(m1 - nm1);
        m0 = nm0; m1 = nm1;
        float s0 = 0.0f, s1 = 0.0f;
        bool dbl = extraFlag && (t == 15);
        #pragma unroll
        for (int ni = 0; ni < 8; ni++) {
            float p00 = __expf(sc[ni][0] - nm0);
            float p01 = __expf(sc[ni][1] - nm0);
            float p10 = __expf(sc[ni][2] - nm1);
            float p11 = __expf(sc[ni][3] - nm1);
            if (dbl && ni >= 6) { p00 *= 2.f; p01 *= 2.f; p10 *= 2.f; p11 *= 2.f; }
            s0 += p00 + p01; s1 += p10 + p11;
            sc[ni][0] = p00; sc[ni][1] = p01; sc[ni][2] = p10; sc[ni][3] = p11;
        }
        s0 += __shfl_xor_sync(0xffffffff, s0, 1);
        s0 += __shfl_xor_sync(0xffffffff, s0, 2);
        s1 += __shfl_xor_sync(0xffffffff, s1, 1);
        s1 += __shfl_xor_sync(0xffffffff, s1, 2);
        l0 = l0 * c0 + s0;
        l1 = l1 * c1 + s1;

        #pragma unroll
        for (int ni = 0; ni < 8; ni++) {
            oacc[ni][0] *= c0; oacc[ni][1] *= c0;
            oacc[ni][2] *= c1; oacc[ni][3] *= c1;
        }
        #pragma unroll
        for (int kki = 0; kki < 4; kki++) {
            int ni0 = 2 * kki;
            unsigned af2[4];
            af2[0] = packh2(sc[ni0][0],     sc[ni0][1]);
            af2[1] = packh2(sc[ni0][2],     sc[ni0][3]);
            af2[2] = packh2(sc[ni0 + 1][0], sc[ni0 + 1][1]);
            af2[3] = packh2(sc[ni0 + 1][2], sc[ni0 + 1][3]);
            #pragma unroll
            for (int g = 0; g < 4; g++) {
                unsigned bf[4];
                ldsm4t(bf, vB + (unsigned)((kki * 16) * FSTR + g * 16 + offV) * 2u);
                mma16(oacc[2 * g],     af2, bf[0], bf[2]);
                mma16(oacc[2 * g + 1], af2, bf[1], bf[3]);
            }
        }
        if (lane == 0) MBAR_ARRIVE(mbE + 8u * s);
    }

    {
        int q = lane >> 2, r2c = (lane & 3) * 2;
        float i0 = 1.0f / l0, i1 = 1.0f / l1;
        int row0 = qrow0 + wm + q;
        #pragma unroll
        for (int ni = 0; ni < 8; ni++) {
            int col = h * 64 + ni * 8 + r2c;
            size_t g0 = (size_t)(b * SEQ + row0) * D_MODEL + col;
            size_t g1 = (size_t)(b * SEQ + row0 + 8) * D_MODEL + col;
            ((__half2*)O)[g0 >> 1] = __floats2half2_rn(oacc[ni][0] * i0, oacc[ni][1] * i0);
            ((__half2*)O)[g1 >> 1] = __floats2half2_rn(oacc[ni][2] * i1, oacc[ni][3] * i1);
        }
    }
}

// ---------------------------------------------------------------------------
// Reductions / LN (fp16 inputs, fp32 statistics)
// ---------------------------------------------------------------------------
__device__ __forceinline__ float block_reduce_sum(float val, float* sdata) {
    int t = threadIdx.x;
    #pragma unroll
    for (int off = 16; off > 0; off >>= 1)
        val += __shfl_down_sync(0xffffffff, val, off);
    if ((t & 31) == 0) sdata[t >> 5] = val;
    __syncthreads();
    if (t < 32) {
        float v = (t < 8) ? sdata[t] : 0.0f;
        #pragma unroll
        for (int off = 4; off > 0; off >>= 1)
            v += __shfl_down_sync(0xffffffff, v, off);
        if (t == 0) sdata[0] = v;
    }
    __syncthreads();
    float r = sdata[0];
    __syncthreads();
    return r;
}

__global__ __launch_bounds__(256)
void ln_kernel(const __half* __restrict__ x, const float* __restrict__ g,
               const float* __restrict__ bb, float* __restrict__ outf,
               __half* __restrict__ outh, float* __restrict__ memout) {
    __shared__ float sdata[32];
    int row = blockIdx.x;
    int t = threadIdx.x;
    const __half* xr = x + (size_t)row * D_MODEL;
    float v[4];
    #pragma unroll
    for (int i = 0; i < 4; i++) v[i] = __half2float(xr[t + 256 * i]);
    float s = v[0] + v[1] + v[2] + v[3];
    float mu = block_reduce_sum(s, sdata) * (1.0f / 1024.0f);
    float sq = 0.f;
    #pragma unroll
    for (int i = 0; i < 4; i++) { float d0 = v[i] - mu; sq += d0 * d0; }
    float var = block_reduce_sum(sq, sdata) * (1.0f / 1024.0f);
    float inv = 1.0f / sqrtf(var + 1e-5f);
    int srow = row & (SEQ - 1), bidx = row >> 10;
    bool isMem = memout && (srow >= 1008);
    float* mrow = isMem ? memout + ((size_t)(bidx * 16 + srow - 1008)) * D_MODEL : nullptr;
    #pragma unroll
    for (int i = 0; i < 4; i++) {
        int c = t + 256 * i;
        float o = (v[i] - mu) * inv * g[c] + bb[c];
        if (outf) outf[(size_t)row * D_MODEL + c] = o;
        if (outh) outh[(size_t)row * D_MODEL + c] = __float2half(o);
        if (isMem) mrow[c] = o;
    }
}

// y = hidsh(fp16) + LN(proj fp16)*g1+b1 ; out_h = fp16(LN(y)*g2+b2)
__global__ __launch_bounds__(256)
void ln_ln_kernel(const __half* __restrict__ proj,
                  const float* __restrict__ g1, const float* __restrict__ b1,
                  const __half* __restrict__ hidsh,
                  const float* __restrict__ g2, const float* __restrict__ b2,
                  __half* __restrict__ outh) {
    __shared__ float sdata[32];
    int row = blockIdx.x;
    int t = threadIdx.x;
    const __half* xr = proj + (size_t)row * D_MODEL;
    const __half* hr = hidsh + (size_t)row * D_MODEL;
    float v[4], hv[4];
    #pragma unroll
    for (int i = 0; i < 4; i++) {
        v[i]  = __half2float(xr[t + 256 * i]);
        hv[i] = __half2float(hr[t + 256 * i]);
    }
    float s = v[0] + v[1] + v[2] + v[3];
    float mu = block_reduce_sum(s, sdata) * (1.0f / 1024.0f);
    float sq = 0.f;
    #pragma unroll
    for (int i = 0; i < 4; i++) { float d0 = v[i] - mu; sq += d0 * d0; }
    float var = block_reduce_sum(sq, sdata) * (1.0f / 1024.0f);
    float inv = 1.0f / sqrtf(var + 1e-5f);
    float y[4];
    #pragma unroll
    for (int i = 0; i < 4; i++) {
        int c = t + 256 * i;
        y[i] = hv[i] + (v[i] - mu) * inv * g1[c] + b1[c];
    }
    float s2 = y[0] + y[1] + y[2] + y[3];
    float mu2 = block_reduce_sum(s2, sdata) * (1.0f / 1024.0f);
    float sq2 = 0.f;
    #pragma unroll
    for (int i = 0; i < 4; i++) { float d0 = y[i] - mu2; sq2 += d0 * d0; }
    float var2 = block_reduce_sum(sq2, sdata) * (1.0f / 1024.0f);
    float inv2 = 1.0f / sqrtf(var2 + 1e-5f);
    #pragma unroll
    for (int i = 0; i < 4; i++) {
        int c = t + 256 * i;
        float o = (y[i] - mu2) * inv2 * g2[c] + b2[c];
        outh[(size_t)row * D_MODEL + c] = __float2half(o);
    }
}

// ---------------------------------------------------------------------------
static float *s_pos = 0;
static __half *s_h0h = 0, *s_qkvh = 0, *s_attnh = 0, *s_projh = 0, *s_hidsh = 0, *s_outh = 0;
static __half *s_wTa = 0, *s_wTo = 0, *s_wTaow = 0, *s_wToow = 0, *s_wTff2 = 0;

static void resolve_scratch() {
    if (s_pos) return;
    cudaGetSymbolAddress((void**)&s_pos,   g_pos);
    cudaGetSymbolAddress((void**)&s_h0h,   g_h0h);
    cudaGetSymbolAddress((void**)&s_qkvh,  g_qkvh);
    cudaGetSymbolAddress((void**)&s_attnh, g_attnh);
    cudaGetSymbolAddress((void**)&s_projh, g_projh);
    cudaGetSymbolAddress((void**)&s_hidsh, g_hidsh);
    cudaGetSymbolAddress((void**)&s_outh,  g_outh);
    cudaGetSymbolAddress((void**)&s_wTa,   g_wTa);
    cudaGetSymbolAddress((void**)&s_wTo,   g_wTo);
    cudaGetSymbolAddress((void**)&s_wTaow, g_wTaow);
    cudaGetSymbolAddress((void**)&s_wToow, g_wToow);
    cudaGetSymbolAddress((void**)&s_wTff2, g_wTff2);
    cudaFuncSetAttribute(gemm_h, cudaFuncAttributeMaxDynamicSharedMemorySize, GSMEM);
    cudaFuncSetAttribute(flash_h, cudaFuncAttributeMaxDynamicSharedMemorySize, FA_SMEM);
}

static void run_attention(const __half* xh, const __half* wT, int extraFlag) {
    // persistent qkv projection: 24x32 = 768 tiles over 296 CTAs
    gemm_h<<<PERSIST_CTAS, 128, GSMEM>>>(
        xh, wT, nullptr, s_qkvh, 1024, 1024, 1024, 3072, 24, 32);
    flash_h<<<dim3(8, BATCH * NHEAD), 256, FA_SMEM>>>(s_qkvh, s_attnh, extraFlag);
}

extern "C" void kernel_launch(void* const* d_in, const int* in_sizes, int n_in,
                              void* d_out, int out_size) {
    const int*   data  = (const int*)d_in[0];
    const float* emb   = (const float*)d_in[2];
    const float* a_qw  = (const float*)d_in[3];
    const float* a_kvw = (const float*)d_in[4];
    const float* a_ow  = (const float*)d_in[5];
    const float* a_g   = (const float*)d_in[6];
    const float* a_b   = (const float*)d_in[7];
    const float* o_qw  = (const float*)d_in[16];
    const float* o_kvw = (const float*)d_in[17];
    const float* o_ow  = (const float*)d_in[18];
    const float* o_g   = (const float*)d_in[19];
    const float* o_b   = (const float*)d_in[20];
    const float* ff2_w = (const float*)d_in[21];
    const float* ln1_g = (const float*)d_in[22];
    const float* ln1_b = (const float*)d_in[23];
    const float* ln2_g = (const float*)d_in[24];
    const float* ln2_b = (const float*)d_in[25];
    float* out = (float*)d_out;

    resolve_scratch();

    TpArgs tp;
    tp.src[0] = a_qw;          tp.dst[0] = s_wTa;               tp.ld[0] = 1024;
    tp.src[1] = a_kvw;         tp.dst[1] = s_wTa + 1024*1024;   tp.ld[1] = 2048;
    tp.src[2] = a_kvw + 1024;  tp.dst[2] = s_wTa + 2*1024*1024; tp.ld[2] = 2048;
    tp.src[3] = o_qw;          tp.dst[3] = s_wTo;               tp.ld[3] = 1024;
    tp.src[4] = o_kvw;         tp.dst[4] = s_wTo + 1024*1024;   tp.ld[4] = 2048;
    tp.src[5] = o_kvw + 1024;  tp.dst[5] = s_wTo + 2*1024*1024; tp.ld[5] = 2048;
    tp.src[6] = a_ow;          tp.dst[6] = s_wTaow;             tp.ld[6] = 1024;
    tp.src[7] = o_ow;          tp.dst[7] = s_wToow;             tp.ld[7] = 1024;
    tp.src[8] = ff2_w;         tp.dst[8] = s_wTff2;             tp.ld[8] = 1024;
    transpose_h_kernel<<<dim3(32, 32, 9), dim3(32, 8)>>>(tp);

    pos_kernel<<<(SEQ * D_MODEL) / 256, 256>>>(s_pos);
    embed_kernel<<<OUT_MAIN / 256, 256>>>(data, emb, s_pos, s_h0h);

    // self attention (layer); residual = h0h (fp16)
    run_attention(s_h0h, s_wTa, 0);
    gemm_h<<<256, 128, GSMEM>>>(
        s_attnh, s_wTaow, s_h0h, s_projh, 1024, 1024, 1024, 1024, 8, 32);
    ln_kernel<<<MROWS, 256>>>(s_projh, a_g, a_b, nullptr, s_hidsh, out + OUT_MAIN);

    // OutputAttn (keys >= 1008 double-weighted); residual = hidsh (fp16)
    run_attention(s_hidsh, s_wTo, 1);
    gemm_h<<<256, 128, GSMEM>>>(
        s_attnh, s_wToow, s_hidsh, s_projh, 1024, 1024, 1024, 1024, 8, 32);
    ln_ln_kernel<<<MROWS, 256>>>(s_projh, o_g, o_b, s_hidsh, ln1_g, ln1_b, s_outh);

    // output = LN(outh @ ff2 + outh, ln2); residual = outh (fp16)
    gemm_h<<<256, 128, GSMEM>>>(
        s_outh, s_wTff2, s_outh, s_projh, 1024, 1024, 1024, 1024, 8, 32);
    ln_kernel<<<MROWS, 256>>>(s_projh, ln2_g, ln2_b, out, nullptr, nullptr);
}